// round 14
// baseline (speedup 1.0000x reference)
#include <cuda_runtime.h>
#include <cuda_fp16.h>
#include <cstdint>
#include <math.h>

#define NNODES 50000
#define NROWPAD 50048
#define NEDGES 800000
#define DIM    128
#define NREL   86
#define NBATCH 2048
#define LDT    136   // fp16 smem stride (elems)
#define LDH    132   // fp32 head smem stride (elems)
#define RGROUP 4     // relations per scorer block

// ---------------- scratch (device globals; no allocation allowed) ------------
__device__ __half g_hh [NROWPAD * DIM];     // layer-1 pre-agg h (fp16)
__device__ float g_h  [NNODES * DIM];       // layer-2 pre-agg h (fp32)
__device__ __half g_x1h[NROWPAD * DIM];     // layer-1 output x1 (fp16)
__device__ float g_dinv[NNODES];
__device__ int   g_cnt [NNODES];
__device__ int   g_rowptr[NNODES + 1];
__device__ int   g_cur [NNODES];
__device__ int   g_col [NEDGES];
__device__ float g_T   [NREL * DIM * DIM];
__device__ __half g_WTh[3 * DIM * DIM];     // W1^T, W2^T, M^T  (fp16 hi)
__device__ __half g_WTl[3 * DIM * DIM];     // lo terms
__device__ __half g_Rh [NREL * DIM * DIM];  // R hi ([f][k] layout)
__device__ __half g_Rl [NREL * DIM * DIM];  // R lo
__device__ __half g_Sh [NREL * DIM * DIM];  // S (single fp16)
__device__ float g_head[NBATCH * DIM];
__device__ __half g_thi[NBATCH * DIM];      // tail (single fp16)

// ==================== helpers ===============================================
__device__ __forceinline__ uint32_t smem_u32(const void* p) {
    uint32_t a;
    asm("{ .reg .u64 t; cvta.to.shared.u64 t, %1; cvt.u32.u64 %0, t; }"
        : "=r"(a) : "l"(p));
    return a;
}

__device__ __forceinline__ void ldm_x4(uint32_t* r, uint32_t addr) {
    asm volatile("ldmatrix.sync.aligned.m8n8.x4.shared.b16 {%0,%1,%2,%3}, [%4];"
                 : "=r"(r[0]), "=r"(r[1]), "=r"(r[2]), "=r"(r[3]) : "r"(addr));
}

__device__ __forceinline__ void mma16816(float* d, const uint32_t* a,
                                         const uint32_t* b) {
    asm volatile(
        "mma.sync.aligned.m16n8k16.row.col.f32.f16.f16.f32 "
        "{%0,%1,%2,%3}, {%4,%5,%6,%7}, {%8,%9}, {%0,%1,%2,%3};"
        : "+f"(d[0]), "+f"(d[1]), "+f"(d[2]), "+f"(d[3])
        : "r"(a[0]), "r"(a[1]), "r"(a[2]), "r"(a[3]), "r"(b[0]), "r"(b[1]));
}

#define CP_ASYNC16(dst, src) \
    asm volatile("cp.async.cg.shared.global [%0], [%1], 16;" \
                 :: "r"(dst), "l"(src) : "memory")
#define CP_COMMIT() asm volatile("cp.async.commit_group;" ::: "memory")
#define CP_WAIT(n)  asm volatile("cp.async.wait_group %0;" :: "n"(n) : "memory")

// split two fp32 -> packed fp16x2 hi + lo (exact 2-term repr)
__device__ __forceinline__ void hcvt2(float a, float b, uint32_t& hi, uint32_t& lo) {
    __half2 h = __floats2half2_rn(a, b);
    float ra = a - __half2float(__low2half(h));
    float rb = b - __half2float(__high2half(h));
    __half2 l = __floats2half2_rn(ra, rb);
    hi = *(uint32_t*)&h;
    lo = *(uint32_t*)&l;
}
__device__ __forceinline__ void hcvt8(const float* v, uint4& hi, uint4& lo) {
    uint32_t h[4], l[4];
#pragma unroll
    for (int i = 0; i < 4; i++) hcvt2(v[2 * i], v[2 * i + 1], h[i], l[i]);
    hi = make_uint4(h[0], h[1], h[2], h[3]);
    lo = make_uint4(l[0], l[1], l[2], l[3]);
}
// single-round 8 fp32 -> 8 fp16
__device__ __forceinline__ uint4 hcvt8s(const float* v) {
    uint32_t h[4];
#pragma unroll
    for (int i = 0; i < 4; i++) {
        __half2 p = __floats2half2_rn(v[2 * i], v[2 * i + 1]);
        h[i] = *(uint32_t*)&p;
    }
    return make_uint4(h[0], h[1], h[2], h[3]);
}

// ==================== CSR build =============================================
__global__ void zero_cnt_kernel(int* cnt, int n) {
    int i = blockIdx.x * blockDim.x + threadIdx.x;
    if (i < n) cnt[i] = 0;
}
__global__ void count_kernel(const int4* __restrict__ dst4, int* cnt, int e4) {
    int i = blockIdx.x * blockDim.x + threadIdx.x;
    if (i < e4) {
        int4 d = dst4[i];
        atomicAdd(&cnt[d.x], 1);
        atomicAdd(&cnt[d.y], 1);
        atomicAdd(&cnt[d.z], 1);
        atomicAdd(&cnt[d.w], 1);
    }
}
__global__ void scan_kernel(const int* __restrict__ cnt, int* rowptr, int* cur,
                            float* dinv, int n) {
    __shared__ int ssum[1024];
    int t = threadIdx.x;
    int chunk = (n + 1023) / 1024;
    int beg = t * chunk, end = min(beg + chunk, n);
    int s = 0;
    for (int i = beg; i < end; i++) s += cnt[i];
    ssum[t] = s;
    __syncthreads();
    for (int off = 1; off < 1024; off <<= 1) {
        int v = (t >= off) ? ssum[t - off] : 0;
        __syncthreads();
        ssum[t] += v;
        __syncthreads();
    }
    int base = (t == 0) ? 0 : ssum[t - 1];
    for (int i = beg; i < end; i++) {
        rowptr[i] = base; cur[i] = base;
        dinv[i] = rsqrtf((float)(cnt[i] + 1));
        base += cnt[i];
    }
    if (t == 1023) rowptr[n] = ssum[1023];
}
__global__ void fill_kernel(const int4* __restrict__ src4,
                            const int4* __restrict__ dst4,
                            int* cur, int* col, int e4) {
    int i = blockIdx.x * blockDim.x + threadIdx.x;
    if (i < e4) {
        int4 d = dst4[i];
        int4 s = src4[i];
        col[atomicAdd(&cur[d.x], 1)] = s.x;
        col[atomicAdd(&cur[d.y], 1)] = s.y;
        col[atomicAdd(&cur[d.z], 1)] = s.z;
        col[atomicAdd(&cur[d.w], 1)] = s.w;
    }
}

// ==================== operand prep ==========================================
__global__ void prepW_kernel(const float* __restrict__ W1,
                             const float* __restrict__ W2,
                             const float* __restrict__ M,
                             __half* outH, __half* outL) {
    int mat = blockIdx.x, t = threadIdx.x;
    const float* src = (mat == 0) ? W1 : (mat == 1) ? W2 : M;
    float v[8];
    for (int g = 0; g < 16; g++) {
#pragma unroll
        for (int j = 0; j < 8; j++) v[j] = src[(g * 8 + j) * 128 + t];
        uint4 hi, lo; hcvt8(v, hi, lo);
        long off = (long)mat * 16384 + t * 128 + g * 8;
        *(uint4*)&outH[off] = hi;
        *(uint4*)&outL[off] = lo;
    }
}

__global__ void prepR_kernel(const float* __restrict__ R,
                             __half* outH, __half* outL) {
    long i = (long)(blockIdx.x * blockDim.x + threadIdx.x) * 8;
    if (i >= (long)NREL * 16384) return;
    float v[8];
    float4 a0 = *(const float4*)&R[i];
    float4 a1 = *(const float4*)&R[i + 4];
    v[0]=a0.x; v[1]=a0.y; v[2]=a0.z; v[3]=a0.w;
    v[4]=a1.x; v[5]=a1.y; v[6]=a1.z; v[7]=a1.w;
    uint4 hi, lo; hcvt8(v, hi, lo);
    *(uint4*)&outH[i] = hi;
    *(uint4*)&outL[i] = lo;
}

// ==================== HMMA GEMM (fp32 A exact-split, 2 or 3 pass) ===========
// (used only off-critical-path for the S precompute chain)
__global__ void __launch_bounds__(256)
gemm_mma(const float* __restrict__ A, long strideA,
         const __half* __restrict__ Bhi, const __half* __restrict__ Blo,
         long strideB,
         float* __restrict__ C, long strideC,
         __half* So, long strideS,
         int rows) {
    extern __shared__ char smem[];
    __half* sAh = (__half*)smem;
    __half* sAl = sAh + 128 * LDT;
    __half* sBh = sAl + 128 * LDT;
    __half* sBl = sBh + 128 * LDT;   // only valid for 4-tile launch

    int t = threadIdx.x, wid = t >> 5, l = t & 31;
    int batch = blockIdx.y;
    const float* Ab = A + (long)batch * strideA;
    const __half* Bhb = Bhi + (long)batch * strideB;
    int row0 = blockIdx.x * 128;

    {
        int rr = t >> 1, hc = (t & 1) * 64;
        int grow = row0 + rr;
        const float* ar = Ab + (long)grow * 128 + hc;
        float v[8];
#pragma unroll
        for (int g = 0; g < 8; g++) {
            if (grow < rows) {
                float4 a0 = *(const float4*)&ar[g * 8];
                float4 a1 = *(const float4*)&ar[g * 8 + 4];
                v[0]=a0.x; v[1]=a0.y; v[2]=a0.z; v[3]=a0.w;
                v[4]=a1.x; v[5]=a1.y; v[6]=a1.z; v[7]=a1.w;
            } else {
#pragma unroll
                for (int j = 0; j < 8; j++) v[j] = 0.f;
            }
            uint4 hi, lo; hcvt8(v, hi, lo);
            int so = rr * LDT + hc + g * 8;
            *(uint4*)&sAh[so] = hi;
            *(uint4*)&sAl[so] = lo;
        }
#pragma unroll
        for (int g = 0; g < 8; g++) {
            long goff = (long)rr * 128 + hc + g * 8;
            int so = rr * LDT + hc + g * 8;
            *(uint4*)&sBh[so] = *(const uint4*)&Bhb[goff];
        }
        if (Blo) {
            const __half* Blb = Blo + (long)batch * strideB;
#pragma unroll
            for (int g = 0; g < 8; g++) {
                long goff = (long)rr * 128 + hc + g * 8;
                int so = rr * LDT + hc + g * 8;
                *(uint4*)&sBl[so] = *(const uint4*)&Blb[goff];
            }
        }
    }
    __syncthreads();

    uint32_t sAh_u = smem_u32(sAh), sAl_u = smem_u32(sAl);
    uint32_t sBh_u = smem_u32(sBh), sBl_u = smem_u32(sBl);

    int wm = wid >> 2, wn = wid & 3;
    int m0 = wm * 64, n0 = wn * 32;
    int arow = l & 15, acol8 = (l >> 4) * 8;
    int brow = (l & 7) + (l >> 4) * 8, bcol = ((l >> 3) & 1) * 8;

    float acc[4][4][4];
#pragma unroll
    for (int mf = 0; mf < 4; mf++)
#pragma unroll
        for (int nf = 0; nf < 4; nf++)
#pragma unroll
            for (int c = 0; c < 4; c++) acc[mf][nf][c] = 0.f;

#pragma unroll
    for (int ks = 0; ks < 8; ks++) {
        int k0 = ks * 16;
        uint32_t ah[4][4], al[4][4], bh[2][4], bl[2][4];
#pragma unroll
        for (int mf = 0; mf < 4; mf++) {
            uint32_t off = (uint32_t)(((m0 + mf * 16 + arow) * LDT + k0 + acol8) * 2);
            ldm_x4(ah[mf], sAh_u + off);
            ldm_x4(al[mf], sAl_u + off);
        }
#pragma unroll
        for (int nh = 0; nh < 2; nh++) {
            uint32_t off = (uint32_t)(((n0 + nh * 16 + brow) * LDT + k0 + bcol) * 2);
            ldm_x4(bh[nh], sBh_u + off);
            if (Blo) ldm_x4(bl[nh], sBl_u + off);
        }
#pragma unroll
        for (int mf = 0; mf < 4; mf++)
#pragma unroll
            for (int nf = 0; nf < 4; nf++) {
                const uint32_t* bp = &bh[nf >> 1][(nf & 1) * 2];
                mma16816(acc[mf][nf], ah[mf], bp);
                mma16816(acc[mf][nf], al[mf], bp);
                if (Blo) {
                    const uint32_t* blp = &bl[nf >> 1][(nf & 1) * 2];
                    mma16816(acc[mf][nf], ah[mf], blp);
                }
            }
    }

    int r01 = l >> 2, cql = (l & 3) * 2;
    if (So) {
        __half* oh = So + (long)batch * strideS;
#pragma unroll
        for (int mf = 0; mf < 4; mf++) {
            int ra = row0 + m0 + mf * 16 + r01, rb = ra + 8;
#pragma unroll
            for (int nf = 0; nf < 4; nf++) {
                int col = n0 + nf * 8 + cql;
                __half2 p0 = __floats2half2_rn(acc[mf][nf][0], acc[mf][nf][1]);
                __half2 p1 = __floats2half2_rn(acc[mf][nf][2], acc[mf][nf][3]);
                *(uint32_t*)&oh[(long)ra * 128 + col] = *(uint32_t*)&p0;
                *(uint32_t*)&oh[(long)rb * 128 + col] = *(uint32_t*)&p1;
            }
        }
    } else {
        float* Cb = C + (long)batch * strideC;
#pragma unroll
        for (int mf = 0; mf < 4; mf++) {
            int ga = row0 + m0 + mf * 16 + r01, gb = ga + 8;
#pragma unroll
            for (int nf = 0; nf < 4; nf++) {
                int col = n0 + nf * 8 + cql;
                if (ga < rows) {
                    float2 v = make_float2(acc[mf][nf][0], acc[mf][nf][1]);
                    *(float2*)&Cb[(long)ga * 128 + col] = v;
                }
                if (gb < rows) {
                    float2 v = make_float2(acc[mf][nf][2], acc[mf][nf][3]);
                    *(float2*)&Cb[(long)gb * 128 + col] = v;
                }
            }
        }
    }
}

// ==================== gemm1: fp32 A -> round fp16, single pass, fp16 out ====
__global__ void __launch_bounds__(256)
gemm1_mma(const float* __restrict__ A, const __half* __restrict__ Bh,
          __half* __restrict__ O, int rows) {
    extern __shared__ char smem[];
    __half* sA = (__half*)smem;
    __half* sB = sA + 128 * LDT;

    int t = threadIdx.x, wid = t >> 5, l = t & 31;
    int row0 = blockIdx.x * 128;

    {
        int rr = t >> 1, hc = (t & 1) * 64;
        int grow = row0 + rr;
        const float* ar = A + (long)grow * 128 + hc;
        float v[8];
#pragma unroll
        for (int g = 0; g < 8; g++) {
            if (grow < rows) {
                float4 a0 = *(const float4*)&ar[g * 8];
                float4 a1 = *(const float4*)&ar[g * 8 + 4];
                v[0]=a0.x; v[1]=a0.y; v[2]=a0.z; v[3]=a0.w;
                v[4]=a1.x; v[5]=a1.y; v[6]=a1.z; v[7]=a1.w;
            } else {
#pragma unroll
                for (int j = 0; j < 8; j++) v[j] = 0.f;
            }
            int so = rr * LDT + hc + g * 8;
            *(uint4*)&sA[so] = hcvt8s(v);
        }
        const __half* br = Bh + (long)rr * 128 + hc;
#pragma unroll
        for (int g = 0; g < 8; g++) {
            int so = rr * LDT + hc + g * 8;
            *(uint4*)&sB[so] = *(const uint4*)&br[g * 8];
        }
    }
    __syncthreads();

    uint32_t sA_u = smem_u32(sA), sB_u = smem_u32(sB);

    int wm = wid >> 2, wn = wid & 3;
    int m0 = wm * 64, n0 = wn * 32;
    int arow = l & 15, acol8 = (l >> 4) * 8;
    int brow = (l & 7) + (l >> 4) * 8, bcol = ((l >> 3) & 1) * 8;

    float acc[4][4][4];
#pragma unroll
    for (int mf = 0; mf < 4; mf++)
#pragma unroll
        for (int nf = 0; nf < 4; nf++)
#pragma unroll
            for (int c = 0; c < 4; c++) acc[mf][nf][c] = 0.f;

#pragma unroll
    for (int ks = 0; ks < 8; ks++) {
        int k0 = ks * 16;
        uint32_t ah[4][4], bf[2][4];
#pragma unroll
        for (int mf = 0; mf < 4; mf++) {
            uint32_t off = (uint32_t)(((m0 + mf * 16 + arow) * LDT + k0 + acol8) * 2);
            ldm_x4(ah[mf], sA_u + off);
        }
#pragma unroll
        for (int nh = 0; nh < 2; nh++) {
            uint32_t off = (uint32_t)(((n0 + nh * 16 + brow) * LDT + k0 + bcol) * 2);
            ldm_x4(bf[nh], sB_u + off);
        }
#pragma unroll
        for (int mf = 0; mf < 4; mf++)
#pragma unroll
            for (int nf = 0; nf < 4; nf++) {
                const uint32_t* bp = &bf[nf >> 1][(nf & 1) * 2];
                mma16816(acc[mf][nf], ah[mf], bp);
            }
    }

    int r01 = l >> 2, cql = (l & 3) * 2;
#pragma unroll
    for (int mf = 0; mf < 4; mf++) {
        int ra = row0 + m0 + mf * 16 + r01, rb = ra + 8;   // padded global rows
#pragma unroll
        for (int nf = 0; nf < 4; nf++) {
            int col = n0 + nf * 8 + cql;
            __half2 p0 = __floats2half2_rn(acc[mf][nf][0], acc[mf][nf][1]);
            __half2 p1 = __floats2half2_rn(acc[mf][nf][2], acc[mf][nf][3]);
            *(uint32_t*)&O[(long)ra * 128 + col] = *(uint32_t*)&p0;
            *(uint32_t*)&O[(long)rb * 128 + col] = *(uint32_t*)&p1;
        }
    }
}

// ==================== gemm2: fp16 A single pass, fp32 out ===================
__global__ void __launch_bounds__(256)
gemm_h_mma(const __half* __restrict__ A,
           const __half* __restrict__ Bh,
           float* __restrict__ C, int rows) {
    extern __shared__ char smem[];
    __half* sA = (__half*)smem;
    __half* sB = sA + 128 * LDT;

    int t = threadIdx.x, wid = t >> 5, l = t & 31;
    int row0 = blockIdx.x * 128;

    {
        int rr = t >> 1, hc = (t & 1) * 64;
        const __half* ar = A + (long)(row0 + rr) * 128 + hc;
#pragma unroll
        for (int g = 0; g < 8; g++) {
            int so = rr * LDT + hc + g * 8;
            *(uint4*)&sA[so] = *(const uint4*)&ar[g * 8];
        }
        const __half* br = Bh + (long)rr * 128 + hc;
#pragma unroll
        for (int g = 0; g < 8; g++) {
            int so = rr * LDT + hc + g * 8;
            *(uint4*)&sB[so] = *(const uint4*)&br[g * 8];
        }
    }
    __syncthreads();

    uint32_t sA_u = smem_u32(sA), sB_u = smem_u32(sB);

    int wm = wid >> 2, wn = wid & 3;
    int m0 = wm * 64, n0 = wn * 32;
    int arow = l & 15, acol8 = (l >> 4) * 8;
    int brow = (l & 7) + (l >> 4) * 8, bcol = ((l >> 3) & 1) * 8;

    float acc[4][4][4];
#pragma unroll
    for (int mf = 0; mf < 4; mf++)
#pragma unroll
        for (int nf = 0; nf < 4; nf++)
#pragma unroll
            for (int c = 0; c < 4; c++) acc[mf][nf][c] = 0.f;

#pragma unroll
    for (int ks = 0; ks < 8; ks++) {
        int k0 = ks * 16;
        uint32_t ah[4][4], bf[2][4];
#pragma unroll
        for (int mf = 0; mf < 4; mf++) {
            uint32_t off = (uint32_t)(((m0 + mf * 16 + arow) * LDT + k0 + acol8) * 2);
            ldm_x4(ah[mf], sA_u + off);
        }
#pragma unroll
        for (int nh = 0; nh < 2; nh++) {
            uint32_t off = (uint32_t)(((n0 + nh * 16 + brow) * LDT + k0 + bcol) * 2);
            ldm_x4(bf[nh], sB_u + off);
        }
#pragma unroll
        for (int mf = 0; mf < 4; mf++)
#pragma unroll
            for (int nf = 0; nf < 4; nf++) {
                const uint32_t* bp = &bf[nf >> 1][(nf & 1) * 2];
                mma16816(acc[mf][nf], ah[mf], bp);
            }
    }

    int r01 = l >> 2, cql = (l & 3) * 2;
#pragma unroll
    for (int mf = 0; mf < 4; mf++) {
        int ga = row0 + m0 + mf * 16 + r01, gb = ga + 8;
#pragma unroll
        for (int nf = 0; nf < 4; nf++) {
            int col = n0 + nf * 8 + cql;
            if (ga < rows) {
                float2 v = make_float2(acc[mf][nf][0], acc[mf][nf][1]);
                *(float2*)&C[(long)ga * 128 + col] = v;
            }
            if (gb < rows) {
                float2 v = make_float2(acc[mf][nf][2], acc[mf][nf][3]);
                *(float2*)&C[(long)gb * 128 + col] = v;
            }
        }
    }
}

// ==================== aggregation (layer 1, fp16 in -> fp16 out) ============
__global__ void agg_kernel(const __half* __restrict__ h,
                           const int* __restrict__ rowptr,
                           const int* __restrict__ col,
                           const float* __restrict__ dinv,
                           const float* __restrict__ bias,
                           __half* __restrict__ out, int n) {
    int warp = (blockIdx.x * blockDim.x + threadIdx.x) >> 5;
    int lane = threadIdx.x & 31;
    if (warp >= n) return;
    int beg = rowptr[warp], end = rowptr[warp + 1];
    float dv = dinv[warp];

    const __half2* sr = (const __half2*)(h + (long)warp * 128) + lane * 2;
    float2 s0f = __half22float2(sr[0]);
    float2 s1f = __half22float2(sr[1]);
    float4 acc = make_float4(dv * s0f.x, dv * s0f.y, dv * s1f.x, dv * s1f.y);

    int e = beg;
    for (; e + 4 <= end; e += 4) {
        int c0 = col[e], c1 = col[e + 1], c2 = col[e + 2], c3 = col[e + 3];
        float w0 = dinv[c0], w1 = dinv[c1], w2 = dinv[c2], w3 = dinv[c3];
        const __half2* r0 = (const __half2*)(h + (long)c0 * 128) + lane * 2;
        const __half2* r1 = (const __half2*)(h + (long)c1 * 128) + lane * 2;
        const __half2* r2 = (const __half2*)(h + (long)c2 * 128) + lane * 2;
        const __half2* r3 = (const __half2*)(h + (long)c3 * 128) + lane * 2;
        float2 a0 = __half22float2(r0[0]), b0 = __half22float2(r0[1]);
        float2 a1 = __half22float2(r1[0]), b1 = __half22float2(r1[1]);
        float2 a2 = __half22float2(r2[0]), b2 = __half22float2(r2[1]);
        float2 a3 = __half22float2(r3[0]), b3 = __half22float2(r3[1]);
        acc.x = fmaf(w0, a0.x, fmaf(w1, a1.x, fmaf(w2, a2.x, fmaf(w3, a3.x, acc.x))));
        acc.y = fmaf(w0, a0.y, fmaf(w1, a1.y, fmaf(w2, a2.y, fmaf(w3, a3.y, acc.y))));
        acc.z = fmaf(w0, b0.x, fmaf(w1, b1.x, fmaf(w2, b2.x, fmaf(w3, b3.x, acc.z))));
        acc.w = fmaf(w0, b0.y, fmaf(w1, b1.y, fmaf(w2, b2.y, fmaf(w3, b3.y, acc.w))));
    }
    for (; e < end; e++) {
        int s = col[e];
        float w = dinv[s];
        const __half2* r = (const __half2*)(h + (long)s * 128) + lane * 2;
        float2 a = __half22float2(r[0]), b = __half22float2(r[1]);
        acc.x = fmaf(w, a.x, acc.x);
        acc.y = fmaf(w, a.y, acc.y);
        acc.z = fmaf(w, b.x, acc.z);
        acc.w = fmaf(w, b.y, acc.w);
    }
    float4 bb = *(const float4*)&bias[lane * 4];
    __half2 p0 = __floats2half2_rn(acc.x * dv + bb.x, acc.y * dv + bb.y);
    __half2 p1 = __floats2half2_rn(acc.z * dv + bb.z, acc.w * dv + bb.w);
    uint32_t* o = (uint32_t*)(out + (long)warp * 128 + lane * 4);
    o[0] = *(uint32_t*)&p0;
    o[1] = *(uint32_t*)&p1;
}

// ==================== batch-only aggregation (layer 2 + gather fused) =======
__global__ void agg_batch_kernel(const float* __restrict__ h,
                                 const int* __restrict__ rowptr,
                                 const int* __restrict__ col,
                                 const float* __restrict__ dinv,
                                 const float* __restrict__ bias,
                                 const int* __restrict__ head,
                                 const int* __restrict__ tail,
                                 float* __restrict__ Hg,
                                 __half* __restrict__ Thi) {
    int gw = (blockIdx.x * blockDim.x + threadIdx.x) >> 5;
    int lane = threadIdx.x & 31;
    if (gw >= 2 * NBATCH) return;
    int b = gw >> 1, which = gw & 1;
    int node = which ? tail[b] : head[b];

    int beg = rowptr[node], end = rowptr[node + 1];
    float dv = dinv[node];

    float4 self = *(const float4*)&h[(long)node * 128 + lane * 4];
    float4 acc = make_float4(dv * self.x, dv * self.y, dv * self.z, dv * self.w);

    int e = beg;
    for (; e + 4 <= end; e += 4) {
        int s0 = col[e], s1 = col[e + 1], s2 = col[e + 2], s3 = col[e + 3];
        float w0 = dinv[s0], w1 = dinv[s1], w2 = dinv[s2], w3 = dinv[s3];
        float4 v0 = *(const float4*)&h[(long)s0 * 128 + lane * 4];
        float4 v1 = *(const float4*)&h[(long)s1 * 128 + lane * 4];
        float4 v2 = *(const float4*)&h[(long)s2 * 128 + lane * 4];
        float4 v3 = *(const float4*)&h[(long)s3 * 128 + lane * 4];
        acc.x = fmaf(w0, v0.x, fmaf(w1, v1.x, fmaf(w2, v2.x, fmaf(w3, v3.x, acc.x))));
        acc.y = fmaf(w0, v0.y, fmaf(w1, v1.y, fmaf(w2, v2.y, fmaf(w3, v3.y, acc.y))));
        acc.z = fmaf(w0, v0.z, fmaf(w1, v1.z, fmaf(w2, v2.z, fmaf(w3, v3.z, acc.z))));
        acc.w = fmaf(w0, v0.w, fmaf(w1, v1.w, fmaf(w2, v2.w, fmaf(w3, v3.w, acc.w))));
    }
    for (; e < end; e++) {
        int s = col[e];
        float w = dinv[s];
        float4 v = *(const float4*)&h[(long)s * 128 + lane * 4];
        acc.x = fmaf(w, v.x, acc.x);
        acc.y = fmaf(w, v.y, acc.y);
        acc.z = fmaf(w, v.z, acc.z);
        acc.w = fmaf(w, v.w, acc.w);
    }
    float4 bb = *(const float4*)&bias[lane * 4];
    float4 res = make_float4(acc.x * dv + bb.x, acc.y * dv + bb.y,
                             acc.z * dv + bb.z, acc.w * dv + bb.w);
    long off = (long)b * 128 + lane * 4;
    if (!which) {
        *(float4*)&Hg[off] = res;
    } else {
        __half2 p0 = __floats2half2_rn(res.x, res.y);
        __half2 p1 = __floats2half2_rn(res.z, res.w);
        *(uint32_t*)&Thi[off] = *(uint32_t*)&p0;
        *(uint32_t*)&Thi[off + 2] = *(uint32_t*)&p1;
    }
}

// ==================== scorer (cp.async double-buffered S) ===================
__global__ void __launch_bounds__(256)
score_mma(const __half* __restrict__ Thi,
          const __half* __restrict__ Sh,
          const float* __restrict__ Hg, float* __restrict__ out) {
    extern __shared__ char smem[];
    __half* sAh = (__half*)smem;
    __half* sB0 = sAh + 128 * LDT;
    __half* sB1 = sB0 + 128 * LDT;
    float* Hs = (float*)(sB1 + 128 * LDT);       // [128][LDH]
    float* out_s = Hs + 128 * LDH;               // [RGROUP][128]

    int t = threadIdx.x, wid = t >> 5, l = t & 31;
    int tile = blockIdx.x, rg = blockIdx.y;
    int rr = t >> 1, hc = (t & 1) * 64;

    uint32_t sB_u[2] = { smem_u32(sB0), smem_u32(sB1) };
    uint32_t stage_dst_base = (uint32_t)((rr * LDT + hc) * 2);

    // prefetch S for first relation of this group
    {
        const __half* src = Sh + (long)(rg * RGROUP) * 16384 + rr * 128 + hc;
        uint32_t dst = sB_u[0] + stage_dst_base;
#pragma unroll
        for (int g = 0; g < 8; g++)
            CP_ASYNC16(dst + g * 16, src + g * 8);
        CP_COMMIT();
    }

    // stage tail tile + head tile; zero out_s
    {
        long base = (long)(tile * 128 + rr) * 128 + hc;
#pragma unroll
        for (int g = 0; g < 8; g++) {
            int so = rr * LDT + hc + g * 8;
            *(uint4*)&sAh[so] = *(const uint4*)&Thi[base + g * 8];
        }
        const float* hr = Hg + (long)(tile * 128 + rr) * 128 + hc;
#pragma unroll
        for (int g = 0; g < 8; g++) {
            float4 v0 = *(const float4*)&hr[g * 8];
            float4 v1 = *(const float4*)&hr[g * 8 + 4];
            int so = rr * LDH + hc + g * 8;
            *(float4*)&Hs[so] = v0;
            *(float4*)&Hs[so + 4] = v1;
        }
        if (t < 128)
#pragma unroll
            for (int i = 0; i < RGROUP; i++) out_s[i * 128 + t] = 0.f;
    }

    uint32_t sAh_u = smem_u32(sAh);

    int wm = wid >> 2, wn = wid & 3;
    int m0 = wm * 64, n0 = wn * 32;
    int arow = l & 15, acol8 = (l >> 4) * 8;
    int brow = (l & 7) + (l >> 4) * 8, bcol = ((l >> 3) & 1) * 8;
    int r01 = l >> 2, cql = (l & 3) * 2;

    int rmax = NREL - rg * RGROUP;
    if (rmax > RGROUP) rmax = RGROUP;

    __syncthreads();

    for (int i = 0; i < rmax; i++) {
        bool pf = (i + 1 < rmax);
        if (pf) {
            const __half* src = Sh + (long)(rg * RGROUP + i + 1) * 16384 + rr * 128 + hc;
            uint32_t dst = sB_u[(i + 1) & 1] + stage_dst_base;
#pragma unroll
            for (int g = 0; g < 8; g++)
                CP_ASYNC16(dst + g * 16, src + g * 8);
            CP_COMMIT();
            CP_WAIT(1);
        } else {
            CP_WAIT(0);
        }
        __syncthreads();

        uint32_t sBc = sB_u[i & 1];
        float acc[4][4][4];
#pragma unroll
        for (int mf = 0; mf < 4; mf++)
#pragma unroll
            for (int nf = 0; nf < 4; nf++)
#pragma unroll
                for (int c = 0; c < 4; c++) acc[mf][nf][c] = 0.f;

#pragma unroll
        for (int ks = 0; ks < 8; ks++) {
            int k0 = ks * 16;
            uint32_t ah[4][4], bf[2][4];
#pragma unroll
            for (int mf = 0; mf < 4; mf++) {
                uint32_t off = (uint32_t)(((m0 + mf * 16 + arow) * LDT + k0 + acol8) * 2);
                ldm_x4(ah[mf], sAh_u + off);
            }
#pragma unroll
            for (int nh = 0; nh < 2; nh++) {
                uint32_t off = (uint32_t)(((n0 + nh * 16 + brow) * LDT + k0 + bcol) * 2);
                ldm_x4(bf[nh], sBc + off);
            }
#pragma unroll
            for (int mf = 0; mf < 4; mf++)
#pragma unroll
                for (int nf = 0; nf < 4; nf++) {
                    const uint32_t* bp = &bf[nf >> 1][(nf & 1) * 2];
                    mma16816(acc[mf][nf], ah[mf], bp);
                }
        }

        float part[4][2];
#pragma unroll
        for (int mf = 0; mf < 4; mf++) { part[mf][0] = 0.f; part[mf][1] = 0.f; }
#pragma unroll
        for (int mf = 0; mf < 4; mf++) {
            int ra = m0 + mf * 16 + r01;
#pragma unroll
            for (int nf = 0; nf < 4; nf++) {
                int col = n0 + nf * 8 + cql;
                float2 h0 = *(float2*)&Hs[ra * LDH + col];
                float2 h1 = *(float2*)&Hs[(ra + 8) * LDH + col];
                part[mf][0] += acc[mf][nf][0] * h0.x + acc[mf][nf][1] * h0.y;
                part[mf][1] += acc[mf][nf][2] * h1.x + acc[mf][nf][3] * h1.y;
            }
        }
#pragma unroll
        for (int mf = 0; mf < 4; mf++) {
#pragma unroll
            for (int hh = 0; hh < 2; hh++) {
                part[mf][hh] += __shfl_xor_sync(0xffffffffu, part[mf][hh], 1);
                part[mf][hh] += __shfl_xor_sync(0xffffffffu, part[mf][hh], 2);
            }
        }
        float* os = out_s + i * 128;
        if ((l & 3) == 0) {
#pragma unroll
            for (int mf = 0; mf < 4; mf++) {
                atomicAdd(&os[m0 + mf * 16 + r01], part[mf][0]);
                atomicAdd(&os[m0 + mf * 16 + r01 + 8], part[mf][1]);
            }
        }
        __syncthreads();
    }

    if (t < 128) {
        long orow = (long)(tile * 128 + t) * NREL + rg * RGROUP;
        for (int i = 0; i < rmax; i++)
            out[orow + i] = out_s[i * 128 + t];
    }
}

// ==================== launch ================================================
extern "C" void kernel_launch(void* const* d_in, const int* in_sizes, int n_in,
                              void* d_out, int out_size) {
    const float* init_emb = (const float*)d_in[0];
    const float* W1       = (const float*)d_in[1];
    const float* b1       = (const float*)d_in[2];
    const float* W2       = (const float*)d_in[3];
    const float* b2       = (const float*)d_in[4];
    const float* Rp       = (const float*)d_in[5];
    const float* Mp       = (const float*)d_in[6];
    const int*   head     = (const int*)d_in[7];
    const int*   tail     = (const int*)d_in[8];
    const int*   ei       = (const int*)d_in[9];
    float* out = (float*)d_out;

    const int* src = ei;
    const int* dst = ei + NEDGES;

    float *p_h, *p_dinv, *p_T, *p_head;
    __half *p_hh, *p_x1h, *p_WTh, *p_WTl, *p_Rh, *p_Rl, *p_Sh, *p_thi;
    int *p_cnt, *p_rowptr, *p_cur, *p_col;
    cudaGetSymbolAddress((void**)&p_hh, g_hh);
    cudaGetSymbolAddress((void**)&p_h, g_h);
    cudaGetSymbolAddress((void**)&p_x1h, g_x1h);
    cudaGetSymbolAddress((void**)&p_dinv, g_dinv);
    cudaGetSymbolAddress((void**)&p_cnt, g_cnt);
    cudaGetSymbolAddress((void**)&p_rowptr, g_rowptr);
    cudaGetSymbolAddress((void**)&p_cur, g_cur);
    cudaGetSymbolAddress((void**)&p_col, g_col);
    cudaGetSymbolAddress((void**)&p_T, g_T);
    cudaGetSymbolAddress((void**)&p_WTh, g_WTh);
    cudaGetSymbolAddress((void**)&p_WTl, g_WTl);
    cudaGetSymbolAddress((void**)&p_Rh, g_Rh);
    cudaGetSymbolAddress((void**)&p_Rl, g_Rl);
    cudaGetSymbolAddress((void**)&p_Sh, g_Sh);
    cudaGetSymbolAddress((void**)&p_head, g_head);
    cudaGetSymbolAddress((void**)&p_thi, g_thi);

    const int GEMM_SMEM4 = 4 * 128 * LDT * 2;                       // 139264
    const int GEMMH_SMEM = 2 * 128 * LDT * 2;                       // 69632
    const int SCORE_SMEM = 3 * 128 * LDT * 2 + 128 * LDH * 4 + RGROUP * 128 * 4;
    cudaFuncSetAttribute(gemm_mma,   cudaFuncAttributeMaxDynamicSharedMemorySize, GEMM_SMEM4);
    cudaFuncSetAttribute(gemm1_mma,  cudaFuncAttributeMaxDynamicSharedMemorySize, GEMMH_SMEM);
    cudaFuncSetAttribute(gemm_h_mma, cudaFuncAttributeMaxDynamicSharedMemorySize, GEMMH_SMEM);
    cudaFuncSetAttribute(score_mma,  cudaFuncAttributeMaxDynamicSharedMemorySize, SCORE_SMEM);

    // ---- fork/join streams for capture-parallel branches ----
    cudaStream_t sB, sC;
    cudaStreamCreateWithFlags(&sB, cudaStreamNonBlocking);
    cudaStreamCreateWithFlags(&sC, cudaStreamNonBlocking);
    cudaEvent_t evRoot, evW, evCSR, evS;
    cudaEventCreateWithFlags(&evRoot, cudaEventDisableTiming);
    cudaEventCreateWithFlags(&evW,    cudaEventDisableTiming);
    cudaEventCreateWithFlags(&evCSR,  cudaEventDisableTiming);
    cudaEventCreateWithFlags(&evS,    cudaEventDisableTiming);

    cudaEventRecord(evRoot, 0);

    // --- branch B: CSR build ---
    cudaStreamWaitEvent(sB, evRoot, 0);
    zero_cnt_kernel<<<(NNODES + 255) / 256, 256, 0, sB>>>(p_cnt, NNODES);
    count_kernel<<<(NEDGES / 4 + 255) / 256, 256, 0, sB>>>(
        (const int4*)dst, p_cnt, NEDGES / 4);
    scan_kernel<<<1, 1024, 0, sB>>>(p_cnt, p_rowptr, p_cur, p_dinv, NNODES);
    fill_kernel<<<(NEDGES / 4 + 255) / 256, 256, 0, sB>>>(
        (const int4*)src, (const int4*)dst, p_cur, p_col, NEDGES / 4);
    cudaEventRecord(evCSR, sB);

    // --- main: weight prep ---
    prepW_kernel<<<3, 128>>>(W1, W2, Mp, p_WTh, p_WTl);
    cudaEventRecord(evW, 0);

    // --- branch C: relation prep + S precompute (3-pass, hidden) ---
    cudaStreamWaitEvent(sC, evRoot, 0);
    prepR_kernel<<<(NREL * 16384 / 8 + 255) / 256, 256, 0, sC>>>(Rp, p_Rh, p_Rl);
    cudaStreamWaitEvent(sC, evW, 0);
    gemm_mma<<<dim3(1, NREL), 256, GEMM_SMEM4, sC>>>(
        Rp, 16384, p_WTh + 2 * 16384, p_WTl + 2 * 16384, 0,
        p_T, 16384, nullptr, 0, 128);
    gemm_mma<<<dim3(1, NREL), 256, GEMM_SMEM4, sC>>>(
        p_T, 16384, p_Rh, p_Rl, 16384,
        nullptr, 0, p_Sh, 16384, 128);
    cudaEventRecord(evS, sC);

    int ntiles = (NNODES + 127) / 128;  // 391
    int agg_blocks = (NNODES * 32 + 255) / 256;

    // --- main chain ---
    gemm1_mma<<<ntiles, 256, GEMMH_SMEM>>>(
        init_emb, p_WTh, p_hh, NNODES);
    cudaStreamWaitEvent(0, evCSR, 0);
    agg_kernel<<<agg_blocks, 256>>>(p_hh, p_rowptr, p_col, p_dinv, b1, p_x1h, NNODES);
    gemm_h_mma<<<ntiles, 256, GEMMH_SMEM>>>(
        p_x1h, p_WTh + 16384, p_h, NNODES);
    agg_batch_kernel<<<(2 * NBATCH * 32 + 255) / 256, 256>>>(
        p_h, p_rowptr, p_col, p_dinv, b2, head, tail, p_head, p_thi);

    cudaStreamWaitEvent(0, evS, 0);
    score_mma<<<dim3(NBATCH / 128, (NREL + RGROUP - 1) / RGROUP), 256, SCORE_SMEM>>>(
        p_thi, p_Sh, p_head, out);

    cudaStreamDestroy(sB);
    cudaStreamDestroy(sC);
    cudaEventDestroy(evRoot);
    cudaEventDestroy(evW);
    cudaEventDestroy(evCSR);
    cudaEventDestroy(evS);
}

// round 15
// speedup vs baseline: 1.0163x; 1.0163x over previous
#include <cuda_runtime.h>
#include <cuda_fp16.h>
#include <cstdint>
#include <math.h>

#define NNODES 50000
#define NROWPAD 50048
#define NEDGES 800000
#define DIM    128
#define NREL   86
#define NBATCH 2048
#define LDT    136   // fp16 smem stride (elems)
#define LDH    132   // fp32 head smem stride (elems)
#define RGROUP 4     // relations per scorer block

// ---------------- scratch (device globals; no allocation allowed) ------------
__device__ __half g_hh [NROWPAD * DIM];     // layer-1 pre-agg h (fp16)
__device__ float g_h  [NNODES * DIM];       // layer-2 pre-agg h (fp32)
__device__ __half g_x1h[NROWPAD * DIM];     // layer-1 output x1 (fp16)
__device__ float g_dinv[NNODES];
__device__ int   g_cnt [NNODES];
__device__ int   g_rowptr[NNODES + 1];
__device__ int   g_cur [NNODES];
__device__ int   g_col [NEDGES];
__device__ float g_T   [NREL * DIM * DIM];
__device__ __half g_WTh[3 * DIM * DIM];     // W1^T, W2^T, M^T  (fp16 hi)
__device__ __half g_WTl[3 * DIM * DIM];     // lo terms
__device__ __half g_Rh [NREL * DIM * DIM];  // R hi ([f][k] layout)
__device__ __half g_Rl [NREL * DIM * DIM];  // R lo
__device__ __half g_Sh [NREL * DIM * DIM];  // S (single fp16)
__device__ float g_head[NBATCH * DIM];
__device__ __half g_thi[NBATCH * DIM];      // tail (single fp16)

// ==================== helpers ===============================================
__device__ __forceinline__ uint32_t smem_u32(const void* p) {
    uint32_t a;
    asm("{ .reg .u64 t; cvta.to.shared.u64 t, %1; cvt.u32.u64 %0, t; }"
        : "=r"(a) : "l"(p));
    return a;
}

__device__ __forceinline__ void ldm_x4(uint32_t* r, uint32_t addr) {
    asm volatile("ldmatrix.sync.aligned.m8n8.x4.shared.b16 {%0,%1,%2,%3}, [%4];"
                 : "=r"(r[0]), "=r"(r[1]), "=r"(r[2]), "=r"(r[3]) : "r"(addr));
}

__device__ __forceinline__ void mma16816(float* d, const uint32_t* a,
                                         const uint32_t* b) {
    asm volatile(
        "mma.sync.aligned.m16n8k16.row.col.f32.f16.f16.f32 "
        "{%0,%1,%2,%3}, {%4,%5,%6,%7}, {%8,%9}, {%0,%1,%2,%3};"
        : "+f"(d[0]), "+f"(d[1]), "+f"(d[2]), "+f"(d[3])
        : "r"(a[0]), "r"(a[1]), "r"(a[2]), "r"(a[3]), "r"(b[0]), "r"(b[1]));
}

#define CP_ASYNC16(dst, src) \
    asm volatile("cp.async.cg.shared.global [%0], [%1], 16;" \
                 :: "r"(dst), "l"(src) : "memory")
#define CP_COMMIT() asm volatile("cp.async.commit_group;" ::: "memory")
#define CP_WAIT(n)  asm volatile("cp.async.wait_group %0;" :: "n"(n) : "memory")

// split two fp32 -> packed fp16x2 hi + lo (exact 2-term repr)
__device__ __forceinline__ void hcvt2(float a, float b, uint32_t& hi, uint32_t& lo) {
    __half2 h = __floats2half2_rn(a, b);
    float ra = a - __half2float(__low2half(h));
    float rb = b - __half2float(__high2half(h));
    __half2 l = __floats2half2_rn(ra, rb);
    hi = *(uint32_t*)&h;
    lo = *(uint32_t*)&l;
}
__device__ __forceinline__ void hcvt8(const float* v, uint4& hi, uint4& lo) {
    uint32_t h[4], l[4];
#pragma unroll
    for (int i = 0; i < 4; i++) hcvt2(v[2 * i], v[2 * i + 1], h[i], l[i]);
    hi = make_uint4(h[0], h[1], h[2], h[3]);
    lo = make_uint4(l[0], l[1], l[2], l[3]);
}

// ==================== CSR build =============================================
__global__ void zero_cnt_kernel(int* cnt, int n) {
    int i = blockIdx.x * blockDim.x + threadIdx.x;
    if (i < n) cnt[i] = 0;
}
__global__ void count_kernel(const int4* __restrict__ dst4, int* cnt, int e4) {
    int i = blockIdx.x * blockDim.x + threadIdx.x;
    if (i < e4) {
        int4 d = dst4[i];
        atomicAdd(&cnt[d.x], 1);
        atomicAdd(&cnt[d.y], 1);
        atomicAdd(&cnt[d.z], 1);
        atomicAdd(&cnt[d.w], 1);
    }
}
__global__ void scan_kernel(const int* __restrict__ cnt, int* rowptr, int* cur,
                            float* dinv, int n) {
    __shared__ int ssum[1024];
    int t = threadIdx.x;
    int chunk = (n + 1023) / 1024;
    int beg = t * chunk, end = min(beg + chunk, n);
    int s = 0;
    for (int i = beg; i < end; i++) s += cnt[i];
    ssum[t] = s;
    __syncthreads();
    for (int off = 1; off < 1024; off <<= 1) {
        int v = (t >= off) ? ssum[t - off] : 0;
        __syncthreads();
        ssum[t] += v;
        __syncthreads();
    }
    int base = (t == 0) ? 0 : ssum[t - 1];
    for (int i = beg; i < end; i++) {
        rowptr[i] = base; cur[i] = base;
        dinv[i] = rsqrtf((float)(cnt[i] + 1));
        base += cnt[i];
    }
    if (t == 1023) rowptr[n] = ssum[1023];
}
__global__ void fill_kernel(const int4* __restrict__ src4,
                            const int4* __restrict__ dst4,
                            int* cur, int* col, int e4) {
    int i = blockIdx.x * blockDim.x + threadIdx.x;
    if (i < e4) {
        int4 d = dst4[i];
        int4 s = src4[i];
        col[atomicAdd(&cur[d.x], 1)] = s.x;
        col[atomicAdd(&cur[d.y], 1)] = s.y;
        col[atomicAdd(&cur[d.z], 1)] = s.z;
        col[atomicAdd(&cur[d.w], 1)] = s.w;
    }
}

// ==================== operand prep ==========================================
__global__ void prepW_kernel(const float* __restrict__ W1,
                             const float* __restrict__ W2,
                             const float* __restrict__ M,
                             __half* outH, __half* outL) {
    int mat = blockIdx.x, t = threadIdx.x;
    const float* src = (mat == 0) ? W1 : (mat == 1) ? W2 : M;
    float v[8];
    for (int g = 0; g < 16; g++) {
#pragma unroll
        for (int j = 0; j < 8; j++) v[j] = src[(g * 8 + j) * 128 + t];
        uint4 hi, lo; hcvt8(v, hi, lo);
        long off = (long)mat * 16384 + t * 128 + g * 8;
        *(uint4*)&outH[off] = hi;
        *(uint4*)&outL[off] = lo;
    }
}

__global__ void prepR_kernel(const float* __restrict__ R,
                             __half* outH, __half* outL) {
    long i = (long)(blockIdx.x * blockDim.x + threadIdx.x) * 8;
    if (i >= (long)NREL * 16384) return;
    float v[8];
    float4 a0 = *(const float4*)&R[i];
    float4 a1 = *(const float4*)&R[i + 4];
    v[0]=a0.x; v[1]=a0.y; v[2]=a0.z; v[3]=a0.w;
    v[4]=a1.x; v[5]=a1.y; v[6]=a1.z; v[7]=a1.w;
    uint4 hi, lo; hcvt8(v, hi, lo);
    *(uint4*)&outH[i] = hi;
    *(uint4*)&outL[i] = lo;
}

// ==================== HMMA GEMM (fp32 A exact-split, 2 or 3 pass) ===========
__global__ void __launch_bounds__(256)
gemm_mma(const float* __restrict__ A, long strideA,
         const __half* __restrict__ Bhi, const __half* __restrict__ Blo,
         long strideB,
         float* __restrict__ C, long strideC,
         __half* So, long strideS,
         int rows) {
    extern __shared__ char smem[];
    __half* sAh = (__half*)smem;
    __half* sAl = sAh + 128 * LDT;
    __half* sBh = sAl + 128 * LDT;
    __half* sBl = sBh + 128 * LDT;   // only valid for 4-tile launch

    int t = threadIdx.x, wid = t >> 5, l = t & 31;
    int batch = blockIdx.y;
    const float* Ab = A + (long)batch * strideA;
    const __half* Bhb = Bhi + (long)batch * strideB;
    int row0 = blockIdx.x * 128;

    {
        int rr = t >> 1, hc = (t & 1) * 64;
        int grow = row0 + rr;
        const float* ar = Ab + (long)grow * 128 + hc;
        float v[8];
#pragma unroll
        for (int g = 0; g < 8; g++) {
            if (grow < rows) {
                float4 a0 = *(const float4*)&ar[g * 8];
                float4 a1 = *(const float4*)&ar[g * 8 + 4];
                v[0]=a0.x; v[1]=a0.y; v[2]=a0.z; v[3]=a0.w;
                v[4]=a1.x; v[5]=a1.y; v[6]=a1.z; v[7]=a1.w;
            } else {
#pragma unroll
                for (int j = 0; j < 8; j++) v[j] = 0.f;
            }
            uint4 hi, lo; hcvt8(v, hi, lo);
            int so = rr * LDT + hc + g * 8;
            *(uint4*)&sAh[so] = hi;
            *(uint4*)&sAl[so] = lo;
        }
#pragma unroll
        for (int g = 0; g < 8; g++) {
            long goff = (long)rr * 128 + hc + g * 8;
            int so = rr * LDT + hc + g * 8;
            *(uint4*)&sBh[so] = *(const uint4*)&Bhb[goff];
        }
        if (Blo) {
            const __half* Blb = Blo + (long)batch * strideB;
#pragma unroll
            for (int g = 0; g < 8; g++) {
                long goff = (long)rr * 128 + hc + g * 8;
                int so = rr * LDT + hc + g * 8;
                *(uint4*)&sBl[so] = *(const uint4*)&Blb[goff];
            }
        }
    }
    __syncthreads();

    uint32_t sAh_u = smem_u32(sAh), sAl_u = smem_u32(sAl);
    uint32_t sBh_u = smem_u32(sBh), sBl_u = smem_u32(sBl);

    int wm = wid >> 2, wn = wid & 3;
    int m0 = wm * 64, n0 = wn * 32;
    int arow = l & 15, acol8 = (l >> 4) * 8;
    int brow = (l & 7) + (l >> 4) * 8, bcol = ((l >> 3) & 1) * 8;

    float acc[4][4][4];
#pragma unroll
    for (int mf = 0; mf < 4; mf++)
#pragma unroll
        for (int nf = 0; nf < 4; nf++)
#pragma unroll
            for (int c = 0; c < 4; c++) acc[mf][nf][c] = 0.f;

#pragma unroll
    for (int ks = 0; ks < 8; ks++) {
        int k0 = ks * 16;
        uint32_t ah[4][4], al[4][4], bh[2][4], bl[2][4];
#pragma unroll
        for (int mf = 0; mf < 4; mf++) {
            uint32_t off = (uint32_t)(((m0 + mf * 16 + arow) * LDT + k0 + acol8) * 2);
            ldm_x4(ah[mf], sAh_u + off);
            ldm_x4(al[mf], sAl_u + off);
        }
#pragma unroll
        for (int nh = 0; nh < 2; nh++) {
            uint32_t off = (uint32_t)(((n0 + nh * 16 + brow) * LDT + k0 + bcol) * 2);
            ldm_x4(bh[nh], sBh_u + off);
            if (Blo) ldm_x4(bl[nh], sBl_u + off);
        }
#pragma unroll
        for (int mf = 0; mf < 4; mf++)
#pragma unroll
            for (int nf = 0; nf < 4; nf++) {
                const uint32_t* bp = &bh[nf >> 1][(nf & 1) * 2];
                mma16816(acc[mf][nf], ah[mf], bp);
                mma16816(acc[mf][nf], al[mf], bp);
                if (Blo) {
                    const uint32_t* blp = &bl[nf >> 1][(nf & 1) * 2];
                    mma16816(acc[mf][nf], ah[mf], blp);
                }
            }
    }

    int r01 = l >> 2, cql = (l & 3) * 2;
    if (So) {
        __half* oh = So + (long)batch * strideS;
#pragma unroll
        for (int mf = 0; mf < 4; mf++) {
            int ra = row0 + m0 + mf * 16 + r01, rb = ra + 8;   // GLOBAL rows (padded)
#pragma unroll
            for (int nf = 0; nf < 4; nf++) {
                int col = n0 + nf * 8 + cql;
                __half2 p0 = __floats2half2_rn(acc[mf][nf][0], acc[mf][nf][1]);
                __half2 p1 = __floats2half2_rn(acc[mf][nf][2], acc[mf][nf][3]);
                *(uint32_t*)&oh[(long)ra * 128 + col] = *(uint32_t*)&p0;
                *(uint32_t*)&oh[(long)rb * 128 + col] = *(uint32_t*)&p1;
            }
        }
    } else {
        float* Cb = C + (long)batch * strideC;
#pragma unroll
        for (int mf = 0; mf < 4; mf++) {
            int ga = row0 + m0 + mf * 16 + r01, gb = ga + 8;
#pragma unroll
            for (int nf = 0; nf < 4; nf++) {
                int col = n0 + nf * 8 + cql;
                if (ga < rows) {
                    float2 v = make_float2(acc[mf][nf][0], acc[mf][nf][1]);
                    *(float2*)&Cb[(long)ga * 128 + col] = v;
                }
                if (gb < rows) {
                    float2 v = make_float2(acc[mf][nf][2], acc[mf][nf][3]);
                    *(float2*)&Cb[(long)gb * 128 + col] = v;
                }
            }
        }
    }
}

// ==================== gemm2: fp16 A single pass, fp32 out ===================
__global__ void __launch_bounds__(256)
gemm_h_mma(const __half* __restrict__ A,
           const __half* __restrict__ Bh,
           float* __restrict__ C, int rows) {
    extern __shared__ char smem[];
    __half* sA = (__half*)smem;
    __half* sB = sA + 128 * LDT;

    int t = threadIdx.x, wid = t >> 5, l = t & 31;
    int row0 = blockIdx.x * 128;

    {
        int rr = t >> 1, hc = (t & 1) * 64;
        const __half* ar = A + (long)(row0 + rr) * 128 + hc;
#pragma unroll
        for (int g = 0; g < 8; g++) {
            int so = rr * LDT + hc + g * 8;
            *(uint4*)&sA[so] = *(const uint4*)&ar[g * 8];
        }
        const __half* br = Bh + (long)rr * 128 + hc;
#pragma unroll
        for (int g = 0; g < 8; g++) {
            int so = rr * LDT + hc + g * 8;
            *(uint4*)&sB[so] = *(const uint4*)&br[g * 8];
        }
    }
    __syncthreads();

    uint32_t sA_u = smem_u32(sA), sB_u = smem_u32(sB);

    int wm = wid >> 2, wn = wid & 3;
    int m0 = wm * 64, n0 = wn * 32;
    int arow = l & 15, acol8 = (l >> 4) * 8;
    int brow = (l & 7) + (l >> 4) * 8, bcol = ((l >> 3) & 1) * 8;

    float acc[4][4][4];
#pragma unroll
    for (int mf = 0; mf < 4; mf++)
#pragma unroll
        for (int nf = 0; nf < 4; nf++)
#pragma unroll
            for (int c = 0; c < 4; c++) acc[mf][nf][c] = 0.f;

#pragma unroll
    for (int ks = 0; ks < 8; ks++) {
        int k0 = ks * 16;
        uint32_t ah[4][4], bf[2][4];
#pragma unroll
        for (int mf = 0; mf < 4; mf++) {
            uint32_t off = (uint32_t)(((m0 + mf * 16 + arow) * LDT + k0 + acol8) * 2);
            ldm_x4(ah[mf], sA_u + off);
        }
#pragma unroll
        for (int nh = 0; nh < 2; nh++) {
            uint32_t off = (uint32_t)(((n0 + nh * 16 + brow) * LDT + k0 + bcol) * 2);
            ldm_x4(bf[nh], sB_u + off);
        }
#pragma unroll
        for (int mf = 0; mf < 4; mf++)
#pragma unroll
            for (int nf = 0; nf < 4; nf++) {
                const uint32_t* bp = &bf[nf >> 1][(nf & 1) * 2];
                mma16816(acc[mf][nf], ah[mf], bp);
            }
    }

    int r01 = l >> 2, cql = (l & 3) * 2;
#pragma unroll
    for (int mf = 0; mf < 4; mf++) {
        int ga = row0 + m0 + mf * 16 + r01, gb = ga + 8;
#pragma unroll
        for (int nf = 0; nf < 4; nf++) {
            int col = n0 + nf * 8 + cql;
            if (ga < rows) {
                float2 v = make_float2(acc[mf][nf][0], acc[mf][nf][1]);
                *(float2*)&C[(long)ga * 128 + col] = v;
            }
            if (gb < rows) {
                float2 v = make_float2(acc[mf][nf][2], acc[mf][nf][3]);
                *(float2*)&C[(long)gb * 128 + col] = v;
            }
        }
    }
}

// ==================== aggregation (layer 1, fp16 in -> fp16 out) ============
// 8-edge unroll with front-batched 8B loads for MLP.
__global__ void agg_kernel(const __half* __restrict__ h,
                           const int* __restrict__ rowptr,
                           const int* __restrict__ col,
                           const float* __restrict__ dinv,
                           const float* __restrict__ bias,
                           __half* __restrict__ out, int n) {
    int warp = (blockIdx.x * blockDim.x + threadIdx.x) >> 5;
    int lane = threadIdx.x & 31;
    if (warp >= n) return;
    int beg = rowptr[warp], end = rowptr[warp + 1];
    float dv = dinv[warp];

    const uint2 sv = *(const uint2*)(h + (long)warp * 128 + lane * 4);
    float2 s0f = __half22float2(*(const __half2*)&sv.x);
    float2 s1f = __half22float2(*(const __half2*)&sv.y);
    float4 acc = make_float4(dv * s0f.x, dv * s0f.y, dv * s1f.x, dv * s1f.y);

    int e = beg;
    for (; e + 8 <= end; e += 8) {
        int c[8];
#pragma unroll
        for (int j = 0; j < 8; j++) c[j] = col[e + j];
        float w[8];
#pragma unroll
        for (int j = 0; j < 8; j++) w[j] = dinv[c[j]];
        uint2 rv[8];
#pragma unroll
        for (int j = 0; j < 8; j++)
            rv[j] = *(const uint2*)(h + (long)c[j] * 128 + lane * 4);
#pragma unroll
        for (int j = 0; j < 8; j++) {
            float2 a = __half22float2(*(const __half2*)&rv[j].x);
            float2 b = __half22float2(*(const __half2*)&rv[j].y);
            acc.x = fmaf(w[j], a.x, acc.x);
            acc.y = fmaf(w[j], a.y, acc.y);
            acc.z = fmaf(w[j], b.x, acc.z);
            acc.w = fmaf(w[j], b.y, acc.w);
        }
    }
    for (; e < end; e++) {
        int s = col[e];
        float w = dinv[s];
        uint2 rv = *(const uint2*)(h + (long)s * 128 + lane * 4);
        float2 a = __half22float2(*(const __half2*)&rv.x);
        float2 b = __half22float2(*(const __half2*)&rv.y);
        acc.x = fmaf(w, a.x, acc.x);
        acc.y = fmaf(w, a.y, acc.y);
        acc.z = fmaf(w, b.x, acc.z);
        acc.w = fmaf(w, b.y, acc.w);
    }
    float4 bb = *(const float4*)&bias[lane * 4];
    __half2 p0 = __floats2half2_rn(acc.x * dv + bb.x, acc.y * dv + bb.y);
    __half2 p1 = __floats2half2_rn(acc.z * dv + bb.z, acc.w * dv + bb.w);
    uint32_t* o = (uint32_t*)(out + (long)warp * 128 + lane * 4);
    o[0] = *(uint32_t*)&p0;
    o[1] = *(uint32_t*)&p1;
}

// ==================== batch-only aggregation (layer 2 + gather fused) =======
__global__ void agg_batch_kernel(const float* __restrict__ h,
                                 const int* __restrict__ rowptr,
                                 const int* __restrict__ col,
                                 const float* __restrict__ dinv,
                                 const float* __restrict__ bias,
                                 const int* __restrict__ head,
                                 const int* __restrict__ tail,
                                 float* __restrict__ Hg,
                                 __half* __restrict__ Thi) {
    int gw = (blockIdx.x * blockDim.x + threadIdx.x) >> 5;
    int lane = threadIdx.x & 31;
    if (gw >= 2 * NBATCH) return;
    int b = gw >> 1, which = gw & 1;
    int node = which ? tail[b] : head[b];

    int beg = rowptr[node], end = rowptr[node + 1];
    float dv = dinv[node];

    float4 self = *(const float4*)&h[(long)node * 128 + lane * 4];
    float4 acc = make_float4(dv * self.x, dv * self.y, dv * self.z, dv * self.w);

    int e = beg;
    for (; e + 4 <= end; e += 4) {
        int s0 = col[e], s1 = col[e + 1], s2 = col[e + 2], s3 = col[e + 3];
        float w0 = dinv[s0], w1 = dinv[s1], w2 = dinv[s2], w3 = dinv[s3];
        float4 v0 = *(const float4*)&h[(long)s0 * 128 + lane * 4];
        float4 v1 = *(const float4*)&h[(long)s1 * 128 + lane * 4];
        float4 v2 = *(const float4*)&h[(long)s2 * 128 + lane * 4];
        float4 v3 = *(const float4*)&h[(long)s3 * 128 + lane * 4];
        acc.x = fmaf(w0, v0.x, fmaf(w1, v1.x, fmaf(w2, v2.x, fmaf(w3, v3.x, acc.x))));
        acc.y = fmaf(w0, v0.y, fmaf(w1, v1.y, fmaf(w2, v2.y, fmaf(w3, v3.y, acc.y))));
        acc.z = fmaf(w0, v0.z, fmaf(w1, v1.z, fmaf(w2, v2.z, fmaf(w3, v3.z, acc.z))));
        acc.w = fmaf(w0, v0.w, fmaf(w1, v1.w, fmaf(w2, v2.w, fmaf(w3, v3.w, acc.w))));
    }
    for (; e < end; e++) {
        int s = col[e];
        float w = dinv[s];
        float4 v = *(const float4*)&h[(long)s * 128 + lane * 4];
        acc.x = fmaf(w, v.x, acc.x);
        acc.y = fmaf(w, v.y, acc.y);
        acc.z = fmaf(w, v.z, acc.z);
        acc.w = fmaf(w, v.w, acc.w);
    }
    float4 bb = *(const float4*)&bias[lane * 4];
    float4 res = make_float4(acc.x * dv + bb.x, acc.y * dv + bb.y,
                             acc.z * dv + bb.z, acc.w * dv + bb.w);
    long off = (long)b * 128 + lane * 4;
    if (!which) {
        *(float4*)&Hg[off] = res;
    } else {
        __half2 p0 = __floats2half2_rn(res.x, res.y);
        __half2 p1 = __floats2half2_rn(res.z, res.w);
        *(uint32_t*)&Thi[off] = *(uint32_t*)&p0;
        *(uint32_t*)&Thi[off + 2] = *(uint32_t*)&p1;
    }
}

// ==================== scorer (cp.async double-buffered S) ===================
__global__ void __launch_bounds__(256)
score_mma(const __half* __restrict__ Thi,
          const __half* __restrict__ Sh,
          const float* __restrict__ Hg, float* __restrict__ out) {
    extern __shared__ char smem[];
    __half* sAh = (__half*)smem;
    __half* sB0 = sAh + 128 * LDT;
    __half* sB1 = sB0 + 128 * LDT;
    float* Hs = (float*)(sB1 + 128 * LDT);       // [128][LDH]
    float* out_s = Hs + 128 * LDH;               // [RGROUP][128]

    int t = threadIdx.x, wid = t >> 5, l = t & 31;
    int tile = blockIdx.x, rg = blockIdx.y;
    int rr = t >> 1, hc = (t & 1) * 64;

    uint32_t sB_u[2] = { smem_u32(sB0), smem_u32(sB1) };
    uint32_t stage_dst_base = (uint32_t)((rr * LDT + hc) * 2);

    // prefetch S for first relation of this group
    {
        const __half* src = Sh + (long)(rg * RGROUP) * 16384 + rr * 128 + hc;
        uint32_t dst = sB_u[0] + stage_dst_base;
#pragma unroll
        for (int g = 0; g < 8; g++)
            CP_ASYNC16(dst + g * 16, src + g * 8);
        CP_COMMIT();
    }

    // stage tail tile + head tile; zero out_s
    {
        long base = (long)(tile * 128 + rr) * 128 + hc;
#pragma unroll
        for (int g = 0; g < 8; g++) {
            int so = rr * LDT + hc + g * 8;
            *(uint4*)&sAh[so] = *(const uint4*)&Thi[base + g * 8];
        }
        const float* hr = Hg + (long)(tile * 128 + rr) * 128 + hc;
#pragma unroll
        for (int g = 0; g < 8; g++) {
            float4 v0 = *(const float4*)&hr[g * 8];
            float4 v1 = *(const float4*)&hr[g * 8 + 4];
            int so = rr * LDH + hc + g * 8;
            *(float4*)&Hs[so] = v0;
            *(float4*)&Hs[so + 4] = v1;
        }
        if (t < 128)
#pragma unroll
            for (int i = 0; i < RGROUP; i++) out_s[i * 128 + t] = 0.f;
    }

    uint32_t sAh_u = smem_u32(sAh);

    int wm = wid >> 2, wn = wid & 3;
    int m0 = wm * 64, n0 = wn * 32;
    int arow = l & 15, acol8 = (l >> 4) * 8;
    int brow = (l & 7) + (l >> 4) * 8, bcol = ((l >> 3) & 1) * 8;
    int r01 = l >> 2, cql = (l & 3) * 2;

    int rmax = NREL - rg * RGROUP;
    if (rmax > RGROUP) rmax = RGROUP;

    __syncthreads();

    for (int i = 0; i < rmax; i++) {
        bool pf = (i + 1 < rmax);
        if (pf) {
            const __half* src = Sh + (long)(rg * RGROUP + i + 1) * 16384 + rr * 128 + hc;
            uint32_t dst = sB_u[(i + 1) & 1] + stage_dst_base;
#pragma unroll
            for (int g = 0; g < 8; g++)
                CP_ASYNC16(dst + g * 16, src + g * 8);
            CP_COMMIT();
            CP_WAIT(1);
        } else {
            CP_WAIT(0);
        }
        __syncthreads();

        uint32_t sBc = sB_u[i & 1];
        float acc[4][4][4];
#pragma unroll
        for (int mf = 0; mf < 4; mf++)
#pragma unroll
            for (int nf = 0; nf < 4; nf++)
#pragma unroll
                for (int c = 0; c < 4; c++) acc[mf][nf][c] = 0.f;

#pragma unroll
        for (int ks = 0; ks < 8; ks++) {
            int k0 = ks * 16;
            uint32_t ah[4][4], bf[2][4];
#pragma unroll
            for (int mf = 0; mf < 4; mf++) {
                uint32_t off = (uint32_t)(((m0 + mf * 16 + arow) * LDT + k0 + acol8) * 2);
                ldm_x4(ah[mf], sAh_u + off);
            }
#pragma unroll
            for (int nh = 0; nh < 2; nh++) {
                uint32_t off = (uint32_t)(((n0 + nh * 16 + brow) * LDT + k0 + bcol) * 2);
                ldm_x4(bf[nh], sBc + off);
            }
#pragma unroll
            for (int mf = 0; mf < 4; mf++)
#pragma unroll
                for (int nf = 0; nf < 4; nf++) {
                    const uint32_t* bp = &bf[nf >> 1][(nf & 1) * 2];
                    mma16816(acc[mf][nf], ah[mf], bp);
                }
        }

        float part[4][2];
#pragma unroll
        for (int mf = 0; mf < 4; mf++) { part[mf][0] = 0.f; part[mf][1] = 0.f; }
#pragma unroll
        for (int mf = 0; mf < 4; mf++) {
            int ra = m0 + mf * 16 + r01;
#pragma unroll
            for (int nf = 0; nf < 4; nf++) {
                int col = n0 + nf * 8 + cql;
                float2 h0 = *(float2*)&Hs[ra * LDH + col];
                float2 h1 = *(float2*)&Hs[(ra + 8) * LDH + col];
                part[mf][0] += acc[mf][nf][0] * h0.x + acc[mf][nf][1] * h0.y;
                part[mf][1] += acc[mf][nf][2] * h1.x + acc[mf][nf][3] * h1.y;
            }
        }
#pragma unroll
        for (int mf = 0; mf < 4; mf++) {
#pragma unroll
            for (int hh = 0; hh < 2; hh++) {
                part[mf][hh] += __shfl_xor_sync(0xffffffffu, part[mf][hh], 1);
                part[mf][hh] += __shfl_xor_sync(0xffffffffu, part[mf][hh], 2);
            }
        }
        float* os = out_s + i * 128;
        if ((l & 3) == 0) {
#pragma unroll
            for (int mf = 0; mf < 4; mf++) {
                atomicAdd(&os[m0 + mf * 16 + r01], part[mf][0]);
                atomicAdd(&os[m0 + mf * 16 + r01 + 8], part[mf][1]);
            }
        }
        __syncthreads();
    }

    if (t < 128) {
        long orow = (long)(tile * 128 + t) * NREL + rg * RGROUP;
        for (int i = 0; i < rmax; i++)
            out[orow + i] = out_s[i * 128 + t];
    }
}

// ==================== launch ================================================
extern "C" void kernel_launch(void* const* d_in, const int* in_sizes, int n_in,
                              void* d_out, int out_size) {
    const float* init_emb = (const float*)d_in[0];
    const float* W1       = (const float*)d_in[1];
    const float* b1       = (const float*)d_in[2];
    const float* W2       = (const float*)d_in[3];
    const float* b2       = (const float*)d_in[4];
    const float* Rp       = (const float*)d_in[5];
    const float* Mp       = (const float*)d_in[6];
    const int*   head     = (const int*)d_in[7];
    const int*   tail     = (const int*)d_in[8];
    const int*   ei       = (const int*)d_in[9];
    float* out = (float*)d_out;

    const int* src = ei;
    const int* dst = ei + NEDGES;

    float *p_h, *p_dinv, *p_T, *p_head;
    __half *p_hh, *p_x1h, *p_WTh, *p_WTl, *p_Rh, *p_Rl, *p_Sh, *p_thi;
    int *p_cnt, *p_rowptr, *p_cur, *p_col;
    cudaGetSymbolAddress((void**)&p_hh, g_hh);
    cudaGetSymbolAddress((void**)&p_h, g_h);
    cudaGetSymbolAddress((void**)&p_x1h, g_x1h);
    cudaGetSymbolAddress((void**)&p_dinv, g_dinv);
    cudaGetSymbolAddress((void**)&p_cnt, g_cnt);
    cudaGetSymbolAddress((void**)&p_rowptr, g_rowptr);
    cudaGetSymbolAddress((void**)&p_cur, g_cur);
    cudaGetSymbolAddress((void**)&p_col, g_col);
    cudaGetSymbolAddress((void**)&p_T, g_T);
    cudaGetSymbolAddress((void**)&p_WTh, g_WTh);
    cudaGetSymbolAddress((void**)&p_WTl, g_WTl);
    cudaGetSymbolAddress((void**)&p_Rh, g_Rh);
    cudaGetSymbolAddress((void**)&p_Rl, g_Rl);
    cudaGetSymbolAddress((void**)&p_Sh, g_Sh);
    cudaGetSymbolAddress((void**)&p_head, g_head);
    cudaGetSymbolAddress((void**)&p_thi, g_thi);

    const int GEMM_SMEM3 = 3 * 128 * LDT * 2;                       // 104448
    const int GEMM_SMEM4 = 4 * 128 * LDT * 2;                       // 139264
    const int GEMMH_SMEM = 2 * 128 * LDT * 2;                       // 69632
    const int SCORE_SMEM = 3 * 128 * LDT * 2 + 128 * LDH * 4 + RGROUP * 128 * 4;
    cudaFuncSetAttribute(gemm_mma,   cudaFuncAttributeMaxDynamicSharedMemorySize, GEMM_SMEM4);
    cudaFuncSetAttribute(gemm_h_mma, cudaFuncAttributeMaxDynamicSharedMemorySize, GEMMH_SMEM);
    cudaFuncSetAttribute(score_mma,  cudaFuncAttributeMaxDynamicSharedMemorySize, SCORE_SMEM);

    // ---- fork/join streams for capture-parallel branches ----
    cudaStream_t sB, sC;
    cudaStreamCreateWithFlags(&sB, cudaStreamNonBlocking);
    cudaStreamCreateWithFlags(&sC, cudaStreamNonBlocking);
    cudaEvent_t evRoot, evW, evCSR, evS;
    cudaEventCreateWithFlags(&evRoot, cudaEventDisableTiming);
    cudaEventCreateWithFlags(&evW,    cudaEventDisableTiming);
    cudaEventCreateWithFlags(&evCSR,  cudaEventDisableTiming);
    cudaEventCreateWithFlags(&evS,    cudaEventDisableTiming);

    cudaEventRecord(evRoot, 0);

    // --- branch B: CSR build ---
    cudaStreamWaitEvent(sB, evRoot, 0);
    zero_cnt_kernel<<<(NNODES + 255) / 256, 256, 0, sB>>>(p_cnt, NNODES);
    count_kernel<<<(NEDGES / 4 + 255) / 256, 256, 0, sB>>>(
        (const int4*)dst, p_cnt, NEDGES / 4);
    scan_kernel<<<1, 1024, 0, sB>>>(p_cnt, p_rowptr, p_cur, p_dinv, NNODES);
    fill_kernel<<<(NEDGES / 4 + 255) / 256, 256, 0, sB>>>(
        (const int4*)src, (const int4*)dst, p_cur, p_col, NEDGES / 4);
    cudaEventRecord(evCSR, sB);

    // --- main: weight prep ---
    prepW_kernel<<<3, 128>>>(W1, W2, Mp, p_WTh, p_WTl);
    cudaEventRecord(evW, 0);

    // --- branch C: relation prep + S precompute (3-pass, hidden) ---
    cudaStreamWaitEvent(sC, evRoot, 0);
    prepR_kernel<<<(NREL * 16384 / 8 + 255) / 256, 256, 0, sC>>>(Rp, p_Rh, p_Rl);
    cudaStreamWaitEvent(sC, evW, 0);
    gemm_mma<<<dim3(1, NREL), 256, GEMM_SMEM4, sC>>>(
        Rp, 16384, p_WTh + 2 * 16384, p_WTl + 2 * 16384, 0,
        p_T, 16384, nullptr, 0, 128);
    gemm_mma<<<dim3(1, NREL), 256, GEMM_SMEM4, sC>>>(
        p_T, 16384, p_Rh, p_Rl, 16384,
        nullptr, 0, p_Sh, 16384, 128);
    cudaEventRecord(evS, sC);

    int ntiles = (NNODES + 127) / 128;  // 391
    int agg_blocks = (NNODES * 32 + 255) / 256;

    // --- main chain ---
    // gemm1: fp32-A exact 2-pass (off critical path; hidden behind CSR branch)
    gemm_mma<<<dim3(ntiles, 1), 256, GEMM_SMEM3>>>(
        init_emb, 0, p_WTh, nullptr, 0, nullptr, 0,
        p_hh, 0, NNODES);
    cudaStreamWaitEvent(0, evCSR, 0);
    agg_kernel<<<agg_blocks, 256>>>(p_hh, p_rowptr, p_col, p_dinv, b1, p_x1h, NNODES);
    gemm_h_mma<<<ntiles, 256, GEMMH_SMEM>>>(
        p_x1h, p_WTh + 16384, p_h, NNODES);
    agg_batch_kernel<<<(2 * NBATCH * 32 + 255) / 256, 256>>>(
        p_h, p_rowptr, p_col, p_dinv, b2, head, tail, p_head, p_thi);

    cudaStreamWaitEvent(0, evS, 0);
    score_mma<<<dim3(NBATCH / 128, (NREL + RGROUP - 1) / RGROUP), 256, SCORE_SMEM>>>(
        p_thi, p_Sh, p_head, out);

    cudaStreamDestroy(sB);
    cudaStreamDestroy(sC);
    cudaEventDestroy(evRoot);
    cudaEventDestroy(evW);
    cudaEventDestroy(evCSR);
    cudaEventDestroy(evS);
}

// round 16
// speedup vs baseline: 1.0545x; 1.0376x over previous
#include <cuda_runtime.h>
#include <cuda_fp16.h>
#include <cstdint>
#include <math.h>

#define NNODES 50000
#define NROWPAD 50048
#define NEDGES 800000
#define DIM    128
#define NREL   86
#define NBATCH 2048
#define LDT    136   // fp16 smem stride (elems)
#define LDH    132   // fp32 head smem stride (elems)
#define RGROUP 4     // relations per scorer block

// ---------------- scratch (device globals; no allocation allowed) ------------
__device__ __half g_hh [NROWPAD * DIM];     // layer-1 pre-agg h (fp16)
__device__ __half g_x1h[NROWPAD * DIM];     // layer-1 output x1 (fp16)
__device__ float g_Z  [2 * NBATCH * DIM];   // batch-aggregated x1 (fp32)
__device__ float g_dinv[NNODES];
__device__ int   g_cnt [NNODES];
__device__ int   g_rowptr[NNODES + 1];
__device__ int   g_cur [NNODES];
__device__ int   g_col [NEDGES];
__device__ float g_T   [NREL * DIM * DIM];
__device__ __half g_WTh[3 * DIM * DIM];     // W1^T, W2^T, M^T  (fp16 hi)
__device__ __half g_WTl[3 * DIM * DIM];     // lo terms
__device__ __half g_Rh [NREL * DIM * DIM];  // R hi ([f][k] layout)
__device__ __half g_Rl [NREL * DIM * DIM];  // R lo
__device__ __half g_Sh [NREL * DIM * DIM];  // S (single fp16)
__device__ float g_head[NBATCH * DIM];
__device__ __half g_thi[NBATCH * DIM];      // tail (single fp16)

// ==================== helpers ===============================================
__device__ __forceinline__ uint32_t smem_u32(const void* p) {
    uint32_t a;
    asm("{ .reg .u64 t; cvta.to.shared.u64 t, %1; cvt.u32.u64 %0, t; }"
        : "=r"(a) : "l"(p));
    return a;
}

__device__ __forceinline__ void ldm_x4(uint32_t* r, uint32_t addr) {
    asm volatile("ldmatrix.sync.aligned.m8n8.x4.shared.b16 {%0,%1,%2,%3}, [%4];"
                 : "=r"(r[0]), "=r"(r[1]), "=r"(r[2]), "=r"(r[3]) : "r"(addr));
}

__device__ __forceinline__ void mma16816(float* d, const uint32_t* a,
                                         const uint32_t* b) {
    asm volatile(
        "mma.sync.aligned.m16n8k16.row.col.f32.f16.f16.f32 "
        "{%0,%1,%2,%3}, {%4,%5,%6,%7}, {%8,%9}, {%0,%1,%2,%3};"
        : "+f"(d[0]), "+f"(d[1]), "+f"(d[2]), "+f"(d[3])
        : "r"(a[0]), "r"(a[1]), "r"(a[2]), "r"(a[3]), "r"(b[0]), "r"(b[1]));
}

#define CP_ASYNC16(dst, src) \
    asm volatile("cp.async.cg.shared.global [%0], [%1], 16;" \
                 :: "r"(dst), "l"(src) : "memory")
#define CP_COMMIT() asm volatile("cp.async.commit_group;" ::: "memory")
#define CP_WAIT(n)  asm volatile("cp.async.wait_group %0;" :: "n"(n) : "memory")

// split two fp32 -> packed fp16x2 hi + lo (exact 2-term repr)
__device__ __forceinline__ void hcvt2(float a, float b, uint32_t& hi, uint32_t& lo) {
    __half2 h = __floats2half2_rn(a, b);
    float ra = a - __half2float(__low2half(h));
    float rb = b - __half2float(__high2half(h));
    __half2 l = __floats2half2_rn(ra, rb);
    hi = *(uint32_t*)&h;
    lo = *(uint32_t*)&l;
}
__device__ __forceinline__ void hcvt8(const float* v, uint4& hi, uint4& lo) {
    uint32_t h[4], l[4];
#pragma unroll
    for (int i = 0; i < 4; i++) hcvt2(v[2 * i], v[2 * i + 1], h[i], l[i]);
    hi = make_uint4(h[0], h[1], h[2], h[3]);
    lo = make_uint4(l[0], l[1], l[2], l[3]);
}

// ==================== CSR build =============================================
__global__ void zero_cnt_kernel(int* cnt, int n) {
    int i = blockIdx.x * blockDim.x + threadIdx.x;
    if (i < n) cnt[i] = 0;
}
// 8 edges per thread, front-batched loads
__global__ void count_kernel(const int4* __restrict__ dst4, int* cnt, int e4) {
    int i = (blockIdx.x * blockDim.x + threadIdx.x) * 2;
    if (i + 1 < e4) {
        int4 d0 = dst4[i];
        int4 d1 = dst4[i + 1];
        atomicAdd(&cnt[d0.x], 1);
        atomicAdd(&cnt[d0.y], 1);
        atomicAdd(&cnt[d0.z], 1);
        atomicAdd(&cnt[d0.w], 1);
        atomicAdd(&cnt[d1.x], 1);
        atomicAdd(&cnt[d1.y], 1);
        atomicAdd(&cnt[d1.z], 1);
        atomicAdd(&cnt[d1.w], 1);
    } else if (i < e4) {
        int4 d0 = dst4[i];
        atomicAdd(&cnt[d0.x], 1);
        atomicAdd(&cnt[d0.y], 1);
        atomicAdd(&cnt[d0.z], 1);
        atomicAdd(&cnt[d0.w], 1);
    }
}
__global__ void scan_kernel(const int* __restrict__ cnt, int* rowptr, int* cur,
                            float* dinv, int n) {
    __shared__ int ssum[1024];
    int t = threadIdx.x;
    int chunk = (n + 1023) / 1024;
    int beg = t * chunk, end = min(beg + chunk, n);
    int s = 0;
    for (int i = beg; i < end; i++) s += cnt[i];
    ssum[t] = s;
    __syncthreads();
    for (int off = 1; off < 1024; off <<= 1) {
        int v = (t >= off) ? ssum[t - off] : 0;
        __syncthreads();
        ssum[t] += v;
        __syncthreads();
    }
    int base = (t == 0) ? 0 : ssum[t - 1];
    for (int i = beg; i < end; i++) {
        rowptr[i] = base; cur[i] = base;
        dinv[i] = rsqrtf((float)(cnt[i] + 1));
        base += cnt[i];
    }
    if (t == 1023) rowptr[n] = ssum[1023];
}
// 8 edges per thread
__global__ void fill_kernel(const int4* __restrict__ src4,
                            const int4* __restrict__ dst4,
                            int* cur, int* col, int e4) {
    int i = (blockIdx.x * blockDim.x + threadIdx.x) * 2;
    if (i + 1 < e4) {
        int4 d0 = dst4[i], d1 = dst4[i + 1];
        int4 s0 = src4[i], s1 = src4[i + 1];
        int p0 = atomicAdd(&cur[d0.x], 1);
        int p1 = atomicAdd(&cur[d0.y], 1);
        int p2 = atomicAdd(&cur[d0.z], 1);
        int p3 = atomicAdd(&cur[d0.w], 1);
        int p4 = atomicAdd(&cur[d1.x], 1);
        int p5 = atomicAdd(&cur[d1.y], 1);
        int p6 = atomicAdd(&cur[d1.z], 1);
        int p7 = atomicAdd(&cur[d1.w], 1);
        col[p0] = s0.x; col[p1] = s0.y; col[p2] = s0.z; col[p3] = s0.w;
        col[p4] = s1.x; col[p5] = s1.y; col[p6] = s1.z; col[p7] = s1.w;
    } else if (i < e4) {
        int4 d0 = dst4[i];
        int4 s0 = src4[i];
        col[atomicAdd(&cur[d0.x], 1)] = s0.x;
        col[atomicAdd(&cur[d0.y], 1)] = s0.y;
        col[atomicAdd(&cur[d0.z], 1)] = s0.z;
        col[atomicAdd(&cur[d0.w], 1)] = s0.w;
    }
}

// ==================== operand prep ==========================================
__global__ void prepW_kernel(const float* __restrict__ W1,
                             const float* __restrict__ W2,
                             const float* __restrict__ M,
                             __half* outH, __half* outL) {
    int mat = blockIdx.x, t = threadIdx.x;
    const float* src = (mat == 0) ? W1 : (mat == 1) ? W2 : M;
    float v[8];
    for (int g = 0; g < 16; g++) {
#pragma unroll
        for (int j = 0; j < 8; j++) v[j] = src[(g * 8 + j) * 128 + t];
        uint4 hi, lo; hcvt8(v, hi, lo);
        long off = (long)mat * 16384 + t * 128 + g * 8;
        *(uint4*)&outH[off] = hi;
        *(uint4*)&outL[off] = lo;
    }
}

__global__ void prepR_kernel(const float* __restrict__ R,
                             __half* outH, __half* outL) {
    long i = (long)(blockIdx.x * blockDim.x + threadIdx.x) * 8;
    if (i >= (long)NREL * 16384) return;
    float v[8];
    float4 a0 = *(const float4*)&R[i];
    float4 a1 = *(const float4*)&R[i + 4];
    v[0]=a0.x; v[1]=a0.y; v[2]=a0.z; v[3]=a0.w;
    v[4]=a1.x; v[5]=a1.y; v[6]=a1.z; v[7]=a1.w;
    uint4 hi, lo; hcvt8(v, hi, lo);
    *(uint4*)&outH[i] = hi;
    *(uint4*)&outL[i] = lo;
}

// ==================== HMMA GEMM (fp32 A exact-split, 2 or 3 pass) ===========
__global__ void __launch_bounds__(256)
gemm_mma(const float* __restrict__ A, long strideA,
         const __half* __restrict__ Bhi, const __half* __restrict__ Blo,
         long strideB,
         float* __restrict__ C, long strideC,
         __half* So, long strideS,
         int rows) {
    extern __shared__ char smem[];
    __half* sAh = (__half*)smem;
    __half* sAl = sAh + 128 * LDT;
    __half* sBh = sAl + 128 * LDT;
    __half* sBl = sBh + 128 * LDT;   // only valid for 4-tile launch

    int t = threadIdx.x, wid = t >> 5, l = t & 31;
    int batch = blockIdx.y;
    const float* Ab = A + (long)batch * strideA;
    const __half* Bhb = Bhi + (long)batch * strideB;
    int row0 = blockIdx.x * 128;

    {
        int rr = t >> 1, hc = (t & 1) * 64;
        int grow = row0 + rr;
        const float* ar = Ab + (long)grow * 128 + hc;
        float v[8];
#pragma unroll
        for (int g = 0; g < 8; g++) {
            if (grow < rows) {
                float4 a0 = *(const float4*)&ar[g * 8];
                float4 a1 = *(const float4*)&ar[g * 8 + 4];
                v[0]=a0.x; v[1]=a0.y; v[2]=a0.z; v[3]=a0.w;
                v[4]=a1.x; v[5]=a1.y; v[6]=a1.z; v[7]=a1.w;
            } else {
#pragma unroll
                for (int j = 0; j < 8; j++) v[j] = 0.f;
            }
            uint4 hi, lo; hcvt8(v, hi, lo);
            int so = rr * LDT + hc + g * 8;
            *(uint4*)&sAh[so] = hi;
            *(uint4*)&sAl[so] = lo;
        }
#pragma unroll
        for (int g = 0; g < 8; g++) {
            long goff = (long)rr * 128 + hc + g * 8;
            int so = rr * LDT + hc + g * 8;
            *(uint4*)&sBh[so] = *(const uint4*)&Bhb[goff];
        }
        if (Blo) {
            const __half* Blb = Blo + (long)batch * strideB;
#pragma unroll
            for (int g = 0; g < 8; g++) {
                long goff = (long)rr * 128 + hc + g * 8;
                int so = rr * LDT + hc + g * 8;
                *(uint4*)&sBl[so] = *(const uint4*)&Blb[goff];
            }
        }
    }
    __syncthreads();

    uint32_t sAh_u = smem_u32(sAh), sAl_u = smem_u32(sAl);
    uint32_t sBh_u = smem_u32(sBh), sBl_u = smem_u32(sBl);

    int wm = wid >> 2, wn = wid & 3;
    int m0 = wm * 64, n0 = wn * 32;
    int arow = l & 15, acol8 = (l >> 4) * 8;
    int brow = (l & 7) + (l >> 4) * 8, bcol = ((l >> 3) & 1) * 8;

    float acc[4][4][4];
#pragma unroll
    for (int mf = 0; mf < 4; mf++)
#pragma unroll
        for (int nf = 0; nf < 4; nf++)
#pragma unroll
            for (int c = 0; c < 4; c++) acc[mf][nf][c] = 0.f;

#pragma unroll
    for (int ks = 0; ks < 8; ks++) {
        int k0 = ks * 16;
        uint32_t ah[4][4], al[4][4], bh[2][4], bl[2][4];
#pragma unroll
        for (int mf = 0; mf < 4; mf++) {
            uint32_t off = (uint32_t)(((m0 + mf * 16 + arow) * LDT + k0 + acol8) * 2);
            ldm_x4(ah[mf], sAh_u + off);
            ldm_x4(al[mf], sAl_u + off);
        }
#pragma unroll
        for (int nh = 0; nh < 2; nh++) {
            uint32_t off = (uint32_t)(((n0 + nh * 16 + brow) * LDT + k0 + bcol) * 2);
            ldm_x4(bh[nh], sBh_u + off);
            if (Blo) ldm_x4(bl[nh], sBl_u + off);
        }
#pragma unroll
        for (int mf = 0; mf < 4; mf++)
#pragma unroll
            for (int nf = 0; nf < 4; nf++) {
                const uint32_t* bp = &bh[nf >> 1][(nf & 1) * 2];
                mma16816(acc[mf][nf], ah[mf], bp);
                mma16816(acc[mf][nf], al[mf], bp);
                if (Blo) {
                    const uint32_t* blp = &bl[nf >> 1][(nf & 1) * 2];
                    mma16816(acc[mf][nf], ah[mf], blp);
                }
            }
    }

    int r01 = l >> 2, cql = (l & 3) * 2;
    if (So) {
        __half* oh = So + (long)batch * strideS;
#pragma unroll
        for (int mf = 0; mf < 4; mf++) {
            int ra = row0 + m0 + mf * 16 + r01, rb = ra + 8;   // GLOBAL rows (padded)
#pragma unroll
            for (int nf = 0; nf < 4; nf++) {
                int col = n0 + nf * 8 + cql;
                __half2 p0 = __floats2half2_rn(acc[mf][nf][0], acc[mf][nf][1]);
                __half2 p1 = __floats2half2_rn(acc[mf][nf][2], acc[mf][nf][3]);
                *(uint32_t*)&oh[(long)ra * 128 + col] = *(uint32_t*)&p0;
                *(uint32_t*)&oh[(long)rb * 128 + col] = *(uint32_t*)&p1;
            }
        }
    } else {
        float* Cb = C + (long)batch * strideC;
#pragma unroll
        for (int mf = 0; mf < 4; mf++) {
            int ga = row0 + m0 + mf * 16 + r01, gb = ga + 8;
#pragma unroll
            for (int nf = 0; nf < 4; nf++) {
                int col = n0 + nf * 8 + cql;
                if (ga < rows) {
                    float2 v = make_float2(acc[mf][nf][0], acc[mf][nf][1]);
                    *(float2*)&Cb[(long)ga * 128 + col] = v;
                }
                if (gb < rows) {
                    float2 v = make_float2(acc[mf][nf][2], acc[mf][nf][3]);
                    *(float2*)&Cb[(long)gb * 128 + col] = v;
                }
            }
        }
    }
}

// ==================== mini batch GEMM: Z[4096,128] @ W2 + b2 ================
// A fp32 exact 2-pass split; epilogue: rows [0,NBATCH) -> fp32 Hg,
// rows [NBATCH,2*NBATCH) -> fp16 Thi. Bias added per column.
__global__ void __launch_bounds__(256)
gemm_batch_mma(const float* __restrict__ A,
               const __half* __restrict__ Bh,
               const float* __restrict__ bias,
               float* __restrict__ Hg, __half* __restrict__ Thi) {
    extern __shared__ char smem[];
    __half* sAh = (__half*)smem;
    __half* sAl = sAh + 128 * LDT;
    __half* sB  = sAl + 128 * LDT;

    int t = threadIdx.x, wid = t >> 5, l = t & 31;
    int row0 = blockIdx.x * 128;

    {
        int rr = t >> 1, hc = (t & 1) * 64;
        const float* ar = A + (long)(row0 + rr) * 128 + hc;
        float v[8];
#pragma unroll
        for (int g = 0; g < 8; g++) {
            float4 a0 = *(const float4*)&ar[g * 8];
            float4 a1 = *(const float4*)&ar[g * 8 + 4];
            v[0]=a0.x; v[1]=a0.y; v[2]=a0.z; v[3]=a0.w;
            v[4]=a1.x; v[5]=a1.y; v[6]=a1.z; v[7]=a1.w;
            uint4 hi, lo; hcvt8(v, hi, lo);
            int so = rr * LDT + hc + g * 8;
            *(uint4*)&sAh[so] = hi;
            *(uint4*)&sAl[so] = lo;
        }
        const __half* br = Bh + (long)rr * 128 + hc;
#pragma unroll
        for (int g = 0; g < 8; g++) {
            int so = rr * LDT + hc + g * 8;
            *(uint4*)&sB[so] = *(const uint4*)&br[g * 8];
        }
    }
    __syncthreads();

    uint32_t sAh_u = smem_u32(sAh), sAl_u = smem_u32(sAl);
    uint32_t sB_u = smem_u32(sB);

    int wm = wid >> 2, wn = wid & 3;
    int m0 = wm * 64, n0 = wn * 32;
    int arow = l & 15, acol8 = (l >> 4) * 8;
    int brow = (l & 7) + (l >> 4) * 8, bcol = ((l >> 3) & 1) * 8;

    float acc[4][4][4];
#pragma unroll
    for (int mf = 0; mf < 4; mf++)
#pragma unroll
        for (int nf = 0; nf < 4; nf++)
#pragma unroll
            for (int c = 0; c < 4; c++) acc[mf][nf][c] = 0.f;

#pragma unroll
    for (int ks = 0; ks < 8; ks++) {
        int k0 = ks * 16;
        uint32_t ah[4][4], al[4][4], bf[2][4];
#pragma unroll
        for (int mf = 0; mf < 4; mf++) {
            uint32_t off = (uint32_t)(((m0 + mf * 16 + arow) * LDT + k0 + acol8) * 2);
            ldm_x4(ah[mf], sAh_u + off);
            ldm_x4(al[mf], sAl_u + off);
        }
#pragma unroll
        for (int nh = 0; nh < 2; nh++) {
            uint32_t off = (uint32_t)(((n0 + nh * 16 + brow) * LDT + k0 + bcol) * 2);
            ldm_x4(bf[nh], sB_u + off);
        }
#pragma unroll
        for (int mf = 0; mf < 4; mf++)
#pragma unroll
            for (int nf = 0; nf < 4; nf++) {
                const uint32_t* bp = &bf[nf >> 1][(nf & 1) * 2];
                mma16816(acc[mf][nf], ah[mf], bp);
                mma16816(acc[mf][nf], al[mf], bp);
            }
    }

    int r01 = l >> 2, cql = (l & 3) * 2;
#pragma unroll
    for (int mf = 0; mf < 4; mf++) {
        int ga = row0 + m0 + mf * 16 + r01, gb = ga + 8;
#pragma unroll
        for (int nf = 0; nf < 4; nf++) {
            int col = n0 + nf * 8 + cql;
            float2 bb = *(const float2*)&bias[col];
            float2 va = make_float2(acc[mf][nf][0] + bb.x, acc[mf][nf][1] + bb.y);
            float2 vb = make_float2(acc[mf][nf][2] + bb.x, acc[mf][nf][3] + bb.y);
            if (ga < NBATCH) {
                *(float2*)&Hg[(long)ga * 128 + col] = va;
            } else {
                __half2 p = __floats2half2_rn(va.x, va.y);
                *(uint32_t*)&Thi[(long)(ga - NBATCH) * 128 + col] = *(uint32_t*)&p;
            }
            if (gb < NBATCH) {
                *(float2*)&Hg[(long)gb * 128 + col] = vb;
            } else {
                __half2 p = __floats2half2_rn(vb.x, vb.y);
                *(uint32_t*)&Thi[(long)(gb - NBATCH) * 128 + col] = *(uint32_t*)&p;
            }
        }
    }
}

// ==================== aggregation (layer 1, fp16 in -> fp16 out) ============
__global__ void agg_kernel(const __half* __restrict__ h,
                           const int* __restrict__ rowptr,
                           const int* __restrict__ col,
                           const float* __restrict__ dinv,
                           const float* __restrict__ bias,
                           __half* __restrict__ out, int n) {
    int warp = (blockIdx.x * blockDim.x + threadIdx.x) >> 5;
    int lane = threadIdx.x & 31;
    if (warp >= n) return;
    int beg = rowptr[warp], end = rowptr[warp + 1];
    float dv = dinv[warp];

    const uint2 sv = *(const uint2*)(h + (long)warp * 128 + lane * 4);
    float2 s0f = __half22float2(*(const __half2*)&sv.x);
    float2 s1f = __half22float2(*(const __half2*)&sv.y);
    float4 acc = make_float4(dv * s0f.x, dv * s0f.y, dv * s1f.x, dv * s1f.y);

    int e = beg;
    for (; e + 8 <= end; e += 8) {
        int c[8];
#pragma unroll
        for (int j = 0; j < 8; j++) c[j] = col[e + j];
        float w[8];
#pragma unroll
        for (int j = 0; j < 8; j++) w[j] = dinv[c[j]];
        uint2 rv[8];
#pragma unroll
        for (int j = 0; j < 8; j++)
            rv[j] = *(const uint2*)(h + (long)c[j] * 128 + lane * 4);
#pragma unroll
        for (int j = 0; j < 8; j++) {
            float2 a = __half22float2(*(const __half2*)&rv[j].x);
            float2 b = __half22float2(*(const __half2*)&rv[j].y);
            acc.x = fmaf(w[j], a.x, acc.x);
            acc.y = fmaf(w[j], a.y, acc.y);
            acc.z = fmaf(w[j], b.x, acc.z);
            acc.w = fmaf(w[j], b.y, acc.w);
        }
    }
    for (; e < end; e++) {
        int s = col[e];
        float w = dinv[s];
        uint2 rv = *(const uint2*)(h + (long)s * 128 + lane * 4);
        float2 a = __half22float2(*(const __half2*)&rv.x);
        float2 b = __half22float2(*(const __half2*)&rv.y);
        acc.x = fmaf(w, a.x, acc.x);
        acc.y = fmaf(w, a.y, acc.y);
        acc.z = fmaf(w, b.x, acc.z);
        acc.w = fmaf(w, b.y, acc.w);
    }
    float4 bb = *(const float4*)&bias[lane * 4];
    __half2 p0 = __floats2half2_rn(acc.x * dv + bb.x, acc.y * dv + bb.y);
    __half2 p1 = __floats2half2_rn(acc.z * dv + bb.z, acc.w * dv + bb.w);
    uint32_t* o = (uint32_t*)(out + (long)warp * 128 + lane * 4);
    o[0] = *(uint32_t*)&p0;
    o[1] = *(uint32_t*)&p1;
}

// ==================== batch aggregation in x1-space =========================
// z[row] = dinv_node * ( sum_s dinv[s]*x1[s] + dinv_node*x1[node] )
// rows [0,NBATCH) = head nodes, [NBATCH,2*NBATCH) = tail nodes. fp32 out, no bias.
__global__ void agg_batch_h_kernel(const __half* __restrict__ x1,
                                   const int* __restrict__ rowptr,
                                   const int* __restrict__ col,
                                   const float* __restrict__ dinv,
                                   const int* __restrict__ head,
                                   const int* __restrict__ tail,
                                   float* __restrict__ Z) {
    int gw = (blockIdx.x * blockDim.x + threadIdx.x) >> 5;
    int lane = threadIdx.x & 31;
    if (gw >= 2 * NBATCH) return;
    int node = (gw < NBATCH) ? head[gw] : tail[gw - NBATCH];

    int beg = rowptr[node], end = rowptr[node + 1];
    float dv = dinv[node];

    const uint2 sv = *(const uint2*)(x1 + (long)node * 128 + lane * 4);
    float2 s0f = __half22float2(*(const __half2*)&sv.x);
    float2 s1f = __half22float2(*(const __half2*)&sv.y);
    float4 acc = make_float4(dv * s0f.x, dv * s0f.y, dv * s1f.x, dv * s1f.y);

    int e = beg;
    for (; e + 8 <= end; e += 8) {
        int c[8];
#pragma unroll
        for (int j = 0; j < 8; j++) c[j] = col[e + j];
        float w[8];
#pragma unroll
        for (int j = 0; j < 8; j++) w[j] = dinv[c[j]];
        uint2 rv[8];
#pragma unroll
        for (int j = 0; j < 8; j++)
            rv[j] = *(const uint2*)(x1 + (long)c[j] * 128 + lane * 4);
#pragma unroll
        for (int j = 0; j < 8; j++) {
            float2 a = __half22float2(*(const __half2*)&rv[j].x);
            float2 b = __half22float2(*(const __half2*)&rv[j].y);
            acc.x = fmaf(w[j], a.x, acc.x);
            acc.y = fmaf(w[j], a.y, acc.y);
            acc.z = fmaf(w[j], b.x, acc.z);
            acc.w = fmaf(w[j], b.y, acc.w);
        }
    }
    for (; e < end; e++) {
        int s = col[e];
        float w = dinv[s];
        uint2 rv = *(const uint2*)(x1 + (long)s * 128 + lane * 4);
        float2 a = __half22float2(*(const __half2*)&rv.x);
        float2 b = __half22float2(*(const __half2*)&rv.y);
        acc.x = fmaf(w, a.x, acc.x);
        acc.y = fmaf(w, a.y, acc.y);
        acc.z = fmaf(w, b.x, acc.z);
        acc.w = fmaf(w, b.y, acc.w);
    }
    *(float4*)&Z[(long)gw * 128 + lane * 4] =
        make_float4(acc.x * dv, acc.y * dv, acc.z * dv, acc.w * dv);
}

// ==================== scorer (cp.async double-buffered S) ===================
__global__ void __launch_bounds__(256)
score_mma(const __half* __restrict__ Thi,
          const __half* __restrict__ Sh,
          const float* __restrict__ Hg, float* __restrict__ out) {
    extern __shared__ char smem[];
    __half* sAh = (__half*)smem;
    __half* sB0 = sAh + 128 * LDT;
    __half* sB1 = sB0 + 128 * LDT;
    float* Hs = (float*)(sB1 + 128 * LDT);       // [128][LDH]
    float* out_s = Hs + 128 * LDH;               // [RGROUP][128]

    int t = threadIdx.x, wid = t >> 5, l = t & 31;
    int tile = blockIdx.x, rg = blockIdx.y;
    int rr = t >> 1, hc = (t & 1) * 64;

    uint32_t sB_u[2] = { smem_u32(sB0), smem_u32(sB1) };
    uint32_t stage_dst_base = (uint32_t)((rr * LDT + hc) * 2);

    // prefetch S for first relation of this group
    {
        const __half* src = Sh + (long)(rg * RGROUP) * 16384 + rr * 128 + hc;
        uint32_t dst = sB_u[0] + stage_dst_base;
#pragma unroll
        for (int g = 0; g < 8; g++)
            CP_ASYNC16(dst + g * 16, src + g * 8);
        CP_COMMIT();
    }

    // stage tail tile + head tile; zero out_s
    {
        long base = (long)(tile * 128 + rr) * 128 + hc;
#pragma unroll
        for (int g = 0; g < 8; g++) {
            int so = rr * LDT + hc + g * 8;
            *(uint4*)&sAh[so] = *(const uint4*)&Thi[base + g * 8];
        }
        const float* hr = Hg + (long)(tile * 128 + rr) * 128 + hc;
#pragma unroll
        for (int g = 0; g < 8; g++) {
            float4 v0 = *(const float4*)&hr[g * 8];
            float4 v1 = *(const float4*)&hr[g * 8 + 4];
            int so = rr * LDH + hc + g * 8;
            *(float4*)&Hs[so] = v0;
            *(float4*)&Hs[so + 4] = v1;
        }
        if (t < 128)
#pragma unroll
            for (int i = 0; i < RGROUP; i++) out_s[i * 128 + t] = 0.f;
    }

    uint32_t sAh_u = smem_u32(sAh);

    int wm = wid >> 2, wn = wid & 3;
    int m0 = wm * 64, n0 = wn * 32;
    int arow = l & 15, acol8 = (l >> 4) * 8;
    int brow = (l & 7) + (l >> 4) * 8, bcol = ((l >> 3) & 1) * 8;
    int r01 = l >> 2, cql = (l & 3) * 2;

    int rmax = NREL - rg * RGROUP;
    if (rmax > RGROUP) rmax = RGROUP;

    __syncthreads();

    for (int i = 0; i < rmax; i++) {
        bool pf = (i + 1 < rmax);
        if (pf) {
            const __half* src = Sh + (long)(rg * RGROUP + i + 1) * 16384 + rr * 128 + hc;
            uint32_t dst = sB_u[(i + 1) & 1] + stage_dst_base;
#pragma unroll
            for (int g = 0; g < 8; g++)
                CP_ASYNC16(dst + g * 16, src + g * 8);
            CP_COMMIT();
            CP_WAIT(1);
        } else {
            CP_WAIT(0);
        }
        __syncthreads();

        uint32_t sBc = sB_u[i & 1];
        float acc[4][4][4];
#pragma unroll
        for (int mf = 0; mf < 4; mf++)
#pragma unroll
            for (int nf = 0; nf < 4; nf++)
#pragma unroll
                for (int c = 0; c < 4; c++) acc[mf][nf][c] = 0.f;

#pragma unroll
        for (int ks = 0; ks < 8; ks++) {
            int k0 = ks * 16;
            uint32_t ah[4][4], bf[2][4];
#pragma unroll
            for (int mf = 0; mf < 4; mf++) {
                uint32_t off = (uint32_t)(((m0 + mf * 16 + arow) * LDT + k0 + acol8) * 2);
                ldm_x4(ah[mf], sAh_u + off);
            }
#pragma unroll
            for (int nh = 0; nh < 2; nh++) {
                uint32_t off = (uint32_t)(((n0 + nh * 16 + brow) * LDT + k0 + bcol) * 2);
                ldm_x4(bf[nh], sBc + off);
            }
#pragma unroll
            for (int mf = 0; mf < 4; mf++)
#pragma unroll
                for (int nf = 0; nf < 4; nf++) {
                    const uint32_t* bp = &bf[nf >> 1][(nf & 1) * 2];
                    mma16816(acc[mf][nf], ah[mf], bp);
                }
        }

        float part[4][2];
#pragma unroll
        for (int mf = 0; mf < 4; mf++) { part[mf][0] = 0.f; part[mf][1] = 0.f; }
#pragma unroll
        for (int mf = 0; mf < 4; mf++) {
            int ra = m0 + mf * 16 + r01;
#pragma unroll
            for (int nf = 0; nf < 4; nf++) {
                int col = n0 + nf * 8 + cql;
                float2 h0 = *(float2*)&Hs[ra * LDH + col];
                float2 h1 = *(float2*)&Hs[(ra + 8) * LDH + col];
                part[mf][0] += acc[mf][nf][0] * h0.x + acc[mf][nf][1] * h0.y;
                part[mf][1] += acc[mf][nf][2] * h1.x + acc[mf][nf][3] * h1.y;
            }
        }
#pragma unroll
        for (int mf = 0; mf < 4; mf++) {
#pragma unroll
            for (int hh = 0; hh < 2; hh++) {
                part[mf][hh] += __shfl_xor_sync(0xffffffffu, part[mf][hh], 1);
                part[mf][hh] += __shfl_xor_sync(0xffffffffu, part[mf][hh], 2);
            }
        }
        float* os = out_s + i * 128;
        if ((l & 3) == 0) {
#pragma unroll
            for (int mf = 0; mf < 4; mf++) {
                atomicAdd(&os[m0 + mf * 16 + r01], part[mf][0]);
                atomicAdd(&os[m0 + mf * 16 + r01 + 8], part[mf][1]);
            }
        }
        __syncthreads();
    }

    if (t < 128) {
        long orow = (long)(tile * 128 + t) * NREL + rg * RGROUP;
        for (int i = 0; i < rmax; i++)
            out[orow + i] = out_s[i * 128 + t];
    }
}

// ==================== launch ================================================
extern "C" void kernel_launch(void* const* d_in, const int* in_sizes, int n_in,
                              void* d_out, int out_size) {
    const float* init_emb = (const float*)d_in[0];
    const float* W1       = (const float*)d_in[1];
    const float* b1       = (const float*)d_in[2];
    const float* W2       = (const float*)d_in[3];
    const float* b2       = (const float*)d_in[4];
    const float* Rp       = (const float*)d_in[5];
    const float* Mp       = (const float*)d_in[6];
    const int*   head     = (const int*)d_in[7];
    const int*   tail     = (const int*)d_in[8];
    const int*   ei       = (const int*)d_in[9];
    float* out = (float*)d_out;

    const int* src = ei;
    const int* dst = ei + NEDGES;

    float *p_Z, *p_dinv, *p_T, *p_head;
    __half *p_hh, *p_x1h, *p_WTh, *p_WTl, *p_Rh, *p_Rl, *p_Sh, *p_thi;
    int *p_cnt, *p_rowptr, *p_cur, *p_col;
    cudaGetSymbolAddress((void**)&p_hh, g_hh);
    cudaGetSymbolAddress((void**)&p_x1h, g_x1h);
    cudaGetSymbolAddress((void**)&p_Z, g_Z);
    cudaGetSymbolAddress((void**)&p_dinv, g_dinv);
    cudaGetSymbolAddress((void**)&p_cnt, g_cnt);
    cudaGetSymbolAddress((void**)&p_rowptr, g_rowptr);
    cudaGetSymbolAddress((void**)&p_cur, g_cur);
    cudaGetSymbolAddress((void**)&p_col, g_col);
    cudaGetSymbolAddress((void**)&p_T, g_T);
    cudaGetSymbolAddress((void**)&p_WTh, g_WTh);
    cudaGetSymbolAddress((void**)&p_WTl, g_WTl);
    cudaGetSymbolAddress((void**)&p_Rh, g_Rh);
    cudaGetSymbolAddress((void**)&p_Rl, g_Rl);
    cudaGetSymbolAddress((void**)&p_Sh, g_Sh);
    cudaGetSymbolAddress((void**)&p_head, g_head);
    cudaGetSymbolAddress((void**)&p_thi, g_thi);

    const int GEMM_SMEM3 = 3 * 128 * LDT * 2;                       // 104448
    const int GEMM_SMEM4 = 4 * 128 * LDT * 2;                       // 139264
    const int SCORE_SMEM = 3 * 128 * LDT * 2 + 128 * LDH * 4 + RGROUP * 128 * 4;
    cudaFuncSetAttribute(gemm_mma,       cudaFuncAttributeMaxDynamicSharedMemorySize, GEMM_SMEM4);
    cudaFuncSetAttribute(gemm_batch_mma, cudaFuncAttributeMaxDynamicSharedMemorySize, GEMM_SMEM3);
    cudaFuncSetAttribute(score_mma,      cudaFuncAttributeMaxDynamicSharedMemorySize, SCORE_SMEM);

    // ---- fork/join streams for capture-parallel branches ----
    cudaStream_t sB, sC;
    cudaStreamCreateWithFlags(&sB, cudaStreamNonBlocking);
    cudaStreamCreateWithFlags(&sC, cudaStreamNonBlocking);
    cudaEvent_t evRoot, evW, evCSR, evS;
    cudaEventCreateWithFlags(&evRoot, cudaEventDisableTiming);
    cudaEventCreateWithFlags(&evW,    cudaEventDisableTiming);
    cudaEventCreateWithFlags(&evCSR,  cudaEventDisableTiming);
    cudaEventCreateWithFlags(&evS,    cudaEventDisableTiming);

    cudaEventRecord(evRoot, 0);

    // --- branch B: CSR build ---
    cudaStreamWaitEvent(sB, evRoot, 0);
    zero_cnt_kernel<<<(NNODES + 255) / 256, 256, 0, sB>>>(p_cnt, NNODES);
    count_kernel<<<(NEDGES / 8 + 255) / 256, 256, 0, sB>>>(
        (const int4*)dst, p_cnt, NEDGES / 4);
    scan_kernel<<<1, 1024, 0, sB>>>(p_cnt, p_rowptr, p_cur, p_dinv, NNODES);
    fill_kernel<<<(NEDGES / 8 + 255) / 256, 256, 0, sB>>>(
        (const int4*)src, (const int4*)dst, p_cur, p_col, NEDGES / 4);
    cudaEventRecord(evCSR, sB);

    // --- main: weight prep ---
    prepW_kernel<<<3, 128>>>(W1, W2, Mp, p_WTh, p_WTl);
    cudaEventRecord(evW, 0);

    // --- branch C: relation prep + S precompute (3-pass, hidden) ---
    cudaStreamWaitEvent(sC, evRoot, 0);
    prepR_kernel<<<(NREL * 16384 / 8 + 255) / 256, 256, 0, sC>>>(Rp, p_Rh, p_Rl);
    cudaStreamWaitEvent(sC, evW, 0);
    gemm_mma<<<dim3(1, NREL), 256, GEMM_SMEM4, sC>>>(
        Rp, 16384, p_WTh + 2 * 16384, p_WTl + 2 * 16384, 0,
        p_T, 16384, nullptr, 0, 128);
    gemm_mma<<<dim3(1, NREL), 256, GEMM_SMEM4, sC>>>(
        p_T, 16384, p_Rh, p_Rl, 16384,
        nullptr, 0, p_Sh, 16384, 128);
    cudaEventRecord(evS, sC);

    int ntiles = (NNODES + 127) / 128;  // 391
    int agg_blocks = (NNODES * 32 + 255) / 256;

    // --- main chain ---
    // gemm1: fp32-A exact 2-pass (off critical path; hidden behind CSR branch)
    gemm_mma<<<dim3(ntiles, 1), 256, GEMM_SMEM3>>>(
        init_emb, 0, p_WTh, nullptr, 0, nullptr, 0,
        p_hh, 0, NNODES);
    cudaStreamWaitEvent(0, evCSR, 0);
    agg_kernel<<<agg_blocks, 256>>>(p_hh, p_rowptr, p_col, p_dinv, b1, p_x1h, NNODES);
    // layer 2 reordered: aggregate in x1-space for batch nodes only,
    // then mini-GEMM (4096 x 128) @ W2 + b2 with mixed epilogue.
    agg_batch_h_kernel<<<(2 * NBATCH * 32 + 255) / 256, 256>>>(
        p_x1h, p_rowptr, p_col, p_dinv, head, tail, p_Z);
    gemm_batch_mma<<<2 * NBATCH / 128, 256, GEMM_SMEM3>>>(
        p_Z, p_WTh + 16384, b2, p_head, p_thi);

    cudaStreamWaitEvent(0, evS, 0);
    score_mma<<<dim3(NBATCH / 128, (NREL + RGROUP - 1) / RGROUP), 256, SCORE_SMEM>>>(
        p_thi, p_Sh, p_head, out);

    cudaStreamDestroy(sB);
    cudaStreamDestroy(sC);
    cudaEventDestroy(evRoot);
    cudaEventDestroy(evW);
    cudaEventDestroy(evCSR);
    cudaEventDestroy(evS);
}

// round 17
// speedup vs baseline: 1.3636x; 1.2931x over previous
#include <cuda_runtime.h>
#include <cuda_fp16.h>
#include <cstdint>
#include <math.h>

#define NNODES 50000
#define NROWPAD 50048
#define NEDGES 800000
#define DIM    128
#define NREL   86
#define NBATCH 2048
#define LDT    136   // fp16 smem stride (elems)
#define LDH    132   // fp32 head smem stride (elems)
#define RGROUP 4     // relations per scorer block
#define NSCANB ((NNODES + 255) / 256)   // 196

// ---------------- scratch (device globals; no allocation allowed) ------------
__device__ __half g_hh [NROWPAD * DIM];     // layer-1 pre-agg h (fp16)
__device__ __half g_x1h[NROWPAD * DIM];     // layer-1 output x1 (fp16)
__device__ float g_Z  [2 * NBATCH * DIM];   // batch-aggregated x1 (fp32)
__device__ float g_dinv[NNODES];
__device__ int   g_cnt [NNODES];
__device__ int   g_bsum[NSCANB];
__device__ int   g_rowptr[NNODES + 1];
__device__ int   g_cur [NNODES];
__device__ int   g_col [NEDGES];
__device__ float g_T   [NREL * DIM * DIM];
__device__ __half g_WTh[3 * DIM * DIM];     // W1^T, W2^T, M^T  (fp16 hi)
__device__ __half g_WTl[3 * DIM * DIM];     // lo terms
__device__ __half g_Rh [NREL * DIM * DIM];  // R hi ([f][k] layout)
__device__ __half g_Rl [NREL * DIM * DIM];  // R lo
__device__ __half g_Sh [NREL * DIM * DIM];  // S (single fp16)
__device__ float g_head[NBATCH * DIM];
__device__ __half g_thi[NBATCH * DIM];      // tail (single fp16)

// ==================== helpers ===============================================
__device__ __forceinline__ uint32_t smem_u32(const void* p) {
    uint32_t a;
    asm("{ .reg .u64 t; cvta.to.shared.u64 t, %1; cvt.u32.u64 %0, t; }"
        : "=r"(a) : "l"(p));
    return a;
}

__device__ __forceinline__ void ldm_x4(uint32_t* r, uint32_t addr) {
    asm volatile("ldmatrix.sync.aligned.m8n8.x4.shared.b16 {%0,%1,%2,%3}, [%4];"
                 : "=r"(r[0]), "=r"(r[1]), "=r"(r[2]), "=r"(r[3]) : "r"(addr));
}

__device__ __forceinline__ void mma16816(float* d, const uint32_t* a,
                                         const uint32_t* b) {
    asm volatile(
        "mma.sync.aligned.m16n8k16.row.col.f32.f16.f16.f32 "
        "{%0,%1,%2,%3}, {%4,%5,%6,%7}, {%8,%9}, {%0,%1,%2,%3};"
        : "+f"(d[0]), "+f"(d[1]), "+f"(d[2]), "+f"(d[3])
        : "r"(a[0]), "r"(a[1]), "r"(a[2]), "r"(a[3]), "r"(b[0]), "r"(b[1]));
}

#define CP_ASYNC16(dst, src) \
    asm volatile("cp.async.cg.shared.global [%0], [%1], 16;" \
                 :: "r"(dst), "l"(src) : "memory")
#define CP_COMMIT() asm volatile("cp.async.commit_group;" ::: "memory")
#define CP_WAIT(n)  asm volatile("cp.async.wait_group %0;" :: "n"(n) : "memory")

// split two fp32 -> packed fp16x2 hi + lo (exact 2-term repr)
__device__ __forceinline__ void hcvt2(float a, float b, uint32_t& hi, uint32_t& lo) {
    __half2 h = __floats2half2_rn(a, b);
    float ra = a - __half2float(__low2half(h));
    float rb = b - __half2float(__high2half(h));
    __half2 l = __floats2half2_rn(ra, rb);
    hi = *(uint32_t*)&h;
    lo = *(uint32_t*)&l;
}
__device__ __forceinline__ void hcvt8(const float* v, uint4& hi, uint4& lo) {
    uint32_t h[4], l[4];
#pragma unroll
    for (int i = 0; i < 4; i++) hcvt2(v[2 * i], v[2 * i + 1], h[i], l[i]);
    hi = make_uint4(h[0], h[1], h[2], h[3]);
    lo = make_uint4(l[0], l[1], l[2], l[3]);
}

// ==================== CSR build =============================================
__global__ void count_kernel(const int4* __restrict__ dst4, int* cnt, int e4) {
    int i = blockIdx.x * blockDim.x + threadIdx.x;
    if (i < e4) {
        int4 d = dst4[i];
        atomicAdd(&cnt[d.x], 1);
        atomicAdd(&cnt[d.y], 1);
        atomicAdd(&cnt[d.z], 1);
        atomicAdd(&cnt[d.w], 1);
    }
}

// ---- three-phase multi-block exclusive scan over cnt ----
__global__ void scanA_kernel(const int* __restrict__ cnt, int* bsum, int n) {
    __shared__ int s[256];
    int t = threadIdx.x;
    int i = blockIdx.x * 256 + t;
    int v = (i < n) ? cnt[i] : 0;
    s[t] = v;
    __syncthreads();
    for (int off = 128; off > 0; off >>= 1) {
        if (t < off) s[t] += s[t + off];
        __syncthreads();
    }
    if (t == 0) bsum[blockIdx.x] = s[0];
}
__global__ void scanB_kernel(int* bsum, int nb) {
    __shared__ int s[256];
    int t = threadIdx.x;
    int v = (t < nb) ? bsum[t] : 0;
    s[t] = v;
    __syncthreads();
    for (int off = 1; off < 256; off <<= 1) {
        int u = (t >= off) ? s[t - off] : 0;
        __syncthreads();
        s[t] += u;
        __syncthreads();
    }
    if (t < nb) bsum[t] = s[t] - v;   // exclusive
}
__global__ void scanC_kernel(const int* __restrict__ cnt,
                             const int* __restrict__ bsum,
                             int* rowptr, int* cur, float* dinv, int n) {
    __shared__ int s[256];
    int t = threadIdx.x;
    int i = blockIdx.x * 256 + t;
    int v = (i < n) ? cnt[i] : 0;
    s[t] = v;
    __syncthreads();
    for (int off = 1; off < 256; off <<= 1) {
        int u = (t >= off) ? s[t - off] : 0;
        __syncthreads();
        s[t] += u;
        __syncthreads();
    }
    int base = bsum[blockIdx.x];
    if (i < n) {
        int ex = base + s[t] - v;
        rowptr[i] = ex;
        cur[i] = ex;
        dinv[i] = rsqrtf((float)(v + 1));
    }
    if (i == n - 1) rowptr[n] = base + s[t];
}

__global__ void fill_kernel(const int4* __restrict__ src4,
                            const int4* __restrict__ dst4,
                            int* cur, int* col, int e4) {
    int i = blockIdx.x * blockDim.x + threadIdx.x;
    if (i < e4) {
        int4 d = dst4[i];
        int4 s = src4[i];
        col[atomicAdd(&cur[d.x], 1)] = s.x;
        col[atomicAdd(&cur[d.y], 1)] = s.y;
        col[atomicAdd(&cur[d.z], 1)] = s.z;
        col[atomicAdd(&cur[d.w], 1)] = s.w;
    }
}

// ==================== operand prep ==========================================
__global__ void prepW_kernel(const float* __restrict__ W1,
                             const float* __restrict__ W2,
                             const float* __restrict__ M,
                             __half* outH, __half* outL) {
    int mat = blockIdx.x, t = threadIdx.x;
    const float* src = (mat == 0) ? W1 : (mat == 1) ? W2 : M;
    float v[8];
    for (int g = 0; g < 16; g++) {
#pragma unroll
        for (int j = 0; j < 8; j++) v[j] = src[(g * 8 + j) * 128 + t];
        uint4 hi, lo; hcvt8(v, hi, lo);
        long off = (long)mat * 16384 + t * 128 + g * 8;
        *(uint4*)&outH[off] = hi;
        *(uint4*)&outL[off] = lo;
    }
}

__global__ void prepR_kernel(const float* __restrict__ R,
                             __half* outH, __half* outL) {
    long i = (long)(blockIdx.x * blockDim.x + threadIdx.x) * 8;
    if (i >= (long)NREL * 16384) return;
    float v[8];
    float4 a0 = *(const float4*)&R[i];
    float4 a1 = *(const float4*)&R[i + 4];
    v[0]=a0.x; v[1]=a0.y; v[2]=a0.z; v[3]=a0.w;
    v[4]=a1.x; v[5]=a1.y; v[6]=a1.z; v[7]=a1.w;
    uint4 hi, lo; hcvt8(v, hi, lo);
    *(uint4*)&outH[i] = hi;
    *(uint4*)&outL[i] = lo;
}

// ==================== HMMA GEMM (fp32 A exact-split, 2 or 3 pass) ===========
__global__ void __launch_bounds__(256)
gemm_mma(const float* __restrict__ A, long strideA,
         const __half* __restrict__ Bhi, const __half* __restrict__ Blo,
         long strideB,
         float* __restrict__ C, long strideC,
         __half* So, long strideS,
         int rows) {
    extern __shared__ char smem[];
    __half* sAh = (__half*)smem;
    __half* sAl = sAh + 128 * LDT;
    __half* sBh = sAl + 128 * LDT;
    __half* sBl = sBh + 128 * LDT;   // only valid for 4-tile launch

    int t = threadIdx.x, wid = t >> 5, l = t & 31;
    int batch = blockIdx.y;
    const float* Ab = A + (long)batch * strideA;
    const __half* Bhb = Bhi + (long)batch * strideB;
    int row0 = blockIdx.x * 128;

    {
        int rr = t >> 1, hc = (t & 1) * 64;
        int grow = row0 + rr;
        const float* ar = Ab + (long)grow * 128 + hc;
        float v[8];
#pragma unroll
        for (int g = 0; g < 8; g++) {
            if (grow < rows) {
                float4 a0 = *(const float4*)&ar[g * 8];
                float4 a1 = *(const float4*)&ar[g * 8 + 4];
                v[0]=a0.x; v[1]=a0.y; v[2]=a0.z; v[3]=a0.w;
                v[4]=a1.x; v[5]=a1.y; v[6]=a1.z; v[7]=a1.w;
            } else {
#pragma unroll
                for (int j = 0; j < 8; j++) v[j] = 0.f;
            }
            uint4 hi, lo; hcvt8(v, hi, lo);
            int so = rr * LDT + hc + g * 8;
            *(uint4*)&sAh[so] = hi;
            *(uint4*)&sAl[so] = lo;
        }
#pragma unroll
        for (int g = 0; g < 8; g++) {
            long goff = (long)rr * 128 + hc + g * 8;
            int so = rr * LDT + hc + g * 8;
            *(uint4*)&sBh[so] = *(const uint4*)&Bhb[goff];
        }
        if (Blo) {
            const __half* Blb = Blo + (long)batch * strideB;
#pragma unroll
            for (int g = 0; g < 8; g++) {
                long goff = (long)rr * 128 + hc + g * 8;
                int so = rr * LDT + hc + g * 8;
                *(uint4*)&sBl[so] = *(const uint4*)&Blb[goff];
            }
        }
    }
    __syncthreads();

    uint32_t sAh_u = smem_u32(sAh), sAl_u = smem_u32(sAl);
    uint32_t sBh_u = smem_u32(sBh), sBl_u = smem_u32(sBl);

    int wm = wid >> 2, wn = wid & 3;
    int m0 = wm * 64, n0 = wn * 32;
    int arow = l & 15, acol8 = (l >> 4) * 8;
    int brow = (l & 7) + (l >> 4) * 8, bcol = ((l >> 3) & 1) * 8;

    float acc[4][4][4];
#pragma unroll
    for (int mf = 0; mf < 4; mf++)
#pragma unroll
        for (int nf = 0; nf < 4; nf++)
#pragma unroll
            for (int c = 0; c < 4; c++) acc[mf][nf][c] = 0.f;

#pragma unroll
    for (int ks = 0; ks < 8; ks++) {
        int k0 = ks * 16;
        uint32_t ah[4][4], al[4][4], bh[2][4], bl[2][4];
#pragma unroll
        for (int mf = 0; mf < 4; mf++) {
            uint32_t off = (uint32_t)(((m0 + mf * 16 + arow) * LDT + k0 + acol8) * 2);
            ldm_x4(ah[mf], sAh_u + off);
            ldm_x4(al[mf], sAl_u + off);
        }
#pragma unroll
        for (int nh = 0; nh < 2; nh++) {
            uint32_t off = (uint32_t)(((n0 + nh * 16 + brow) * LDT + k0 + bcol) * 2);
            ldm_x4(bh[nh], sBh_u + off);
            if (Blo) ldm_x4(bl[nh], sBl_u + off);
        }
#pragma unroll
        for (int mf = 0; mf < 4; mf++)
#pragma unroll
            for (int nf = 0; nf < 4; nf++) {
                const uint32_t* bp = &bh[nf >> 1][(nf & 1) * 2];
                mma16816(acc[mf][nf], ah[mf], bp);
                mma16816(acc[mf][nf], al[mf], bp);
                if (Blo) {
                    const uint32_t* blp = &bl[nf >> 1][(nf & 1) * 2];
                    mma16816(acc[mf][nf], ah[mf], blp);
                }
            }
    }

    int r01 = l >> 2, cql = (l & 3) * 2;
    if (So) {
        __half* oh = So + (long)batch * strideS;
#pragma unroll
        for (int mf = 0; mf < 4; mf++) {
            int ra = row0 + m0 + mf * 16 + r01, rb = ra + 8;   // GLOBAL rows (padded)
#pragma unroll
            for (int nf = 0; nf < 4; nf++) {
                int col = n0 + nf * 8 + cql;
                __half2 p0 = __floats2half2_rn(acc[mf][nf][0], acc[mf][nf][1]);
                __half2 p1 = __floats2half2_rn(acc[mf][nf][2], acc[mf][nf][3]);
                *(uint32_t*)&oh[(long)ra * 128 + col] = *(uint32_t*)&p0;
                *(uint32_t*)&oh[(long)rb * 128 + col] = *(uint32_t*)&p1;
            }
        }
    } else {
        float* Cb = C + (long)batch * strideC;
#pragma unroll
        for (int mf = 0; mf < 4; mf++) {
            int ga = row0 + m0 + mf * 16 + r01, gb = ga + 8;
#pragma unroll
            for (int nf = 0; nf < 4; nf++) {
                int col = n0 + nf * 8 + cql;
                if (ga < rows) {
                    float2 v = make_float2(acc[mf][nf][0], acc[mf][nf][1]);
                    *(float2*)&Cb[(long)ga * 128 + col] = v;
                }
                if (gb < rows) {
                    float2 v = make_float2(acc[mf][nf][2], acc[mf][nf][3]);
                    *(float2*)&Cb[(long)gb * 128 + col] = v;
                }
            }
        }
    }
}

// ==================== mini batch GEMM: Z[4096,128] @ W2 + b2 ================
__global__ void __launch_bounds__(256)
gemm_batch_mma(const float* __restrict__ A,
               const __half* __restrict__ Bh,
               const float* __restrict__ bias,
               float* __restrict__ Hg, __half* __restrict__ Thi) {
    extern __shared__ char smem[];
    __half* sAh = (__half*)smem;
    __half* sAl = sAh + 128 * LDT;
    __half* sB  = sAl + 128 * LDT;

    int t = threadIdx.x, wid = t >> 5, l = t & 31;
    int row0 = blockIdx.x * 128;

    {
        int rr = t >> 1, hc = (t & 1) * 64;
        const float* ar = A + (long)(row0 + rr) * 128 + hc;
        float v[8];
#pragma unroll
        for (int g = 0; g < 8; g++) {
            float4 a0 = *(const float4*)&ar[g * 8];
            float4 a1 = *(const float4*)&ar[g * 8 + 4];
            v[0]=a0.x; v[1]=a0.y; v[2]=a0.z; v[3]=a0.w;
            v[4]=a1.x; v[5]=a1.y; v[6]=a1.z; v[7]=a1.w;
            uint4 hi, lo; hcvt8(v, hi, lo);
            int so = rr * LDT + hc + g * 8;
            *(uint4*)&sAh[so] = hi;
            *(uint4*)&sAl[so] = lo;
        }
        const __half* br = Bh + (long)rr * 128 + hc;
#pragma unroll
        for (int g = 0; g < 8; g++) {
            int so = rr * LDT + hc + g * 8;
            *(uint4*)&sB[so] = *(const uint4*)&br[g * 8];
        }
    }
    __syncthreads();

    uint32_t sAh_u = smem_u32(sAh), sAl_u = smem_u32(sAl);
    uint32_t sB_u = smem_u32(sB);

    int wm = wid >> 2, wn = wid & 3;
    int m0 = wm * 64, n0 = wn * 32;
    int arow = l & 15, acol8 = (l >> 4) * 8;
    int brow = (l & 7) + (l >> 4) * 8, bcol = ((l >> 3) & 1) * 8;

    float acc[4][4][4];
#pragma unroll
    for (int mf = 0; mf < 4; mf++)
#pragma unroll
        for (int nf = 0; nf < 4; nf++)
#pragma unroll
            for (int c = 0; c < 4; c++) acc[mf][nf][c] = 0.f;

#pragma unroll
    for (int ks = 0; ks < 8; ks++) {
        int k0 = ks * 16;
        uint32_t ah[4][4], al[4][4], bf[2][4];
#pragma unroll
        for (int mf = 0; mf < 4; mf++) {
            uint32_t off = (uint32_t)(((m0 + mf * 16 + arow) * LDT + k0 + acol8) * 2);
            ldm_x4(ah[mf], sAh_u + off);
            ldm_x4(al[mf], sAl_u + off);
        }
#pragma unroll
        for (int nh = 0; nh < 2; nh++) {
            uint32_t off = (uint32_t)(((n0 + nh * 16 + brow) * LDT + k0 + bcol) * 2);
            ldm_x4(bf[nh], sB_u + off);
        }
#pragma unroll
        for (int mf = 0; mf < 4; mf++)
#pragma unroll
            for (int nf = 0; nf < 4; nf++) {
                const uint32_t* bp = &bf[nf >> 1][(nf & 1) * 2];
                mma16816(acc[mf][nf], ah[mf], bp);
                mma16816(acc[mf][nf], al[mf], bp);
            }
    }

    int r01 = l >> 2, cql = (l & 3) * 2;
#pragma unroll
    for (int mf = 0; mf < 4; mf++) {
        int ga = row0 + m0 + mf * 16 + r01, gb = ga + 8;
#pragma unroll
        for (int nf = 0; nf < 4; nf++) {
            int col = n0 + nf * 8 + cql;
            float2 bb = *(const float2*)&bias[col];
            float2 va = make_float2(acc[mf][nf][0] + bb.x, acc[mf][nf][1] + bb.y);
            float2 vb = make_float2(acc[mf][nf][2] + bb.x, acc[mf][nf][3] + bb.y);
            if (ga < NBATCH) {
                *(float2*)&Hg[(long)ga * 128 + col] = va;
            } else {
                __half2 p = __floats2half2_rn(va.x, va.y);
                *(uint32_t*)&Thi[(long)(ga - NBATCH) * 128 + col] = *(uint32_t*)&p;
            }
            if (gb < NBATCH) {
                *(float2*)&Hg[(long)gb * 128 + col] = vb;
            } else {
                __half2 p = __floats2half2_rn(vb.x, vb.y);
                *(uint32_t*)&Thi[(long)(gb - NBATCH) * 128 + col] = *(uint32_t*)&p;
            }
        }
    }
}

// ==================== aggregation (layer 1, fp16 in -> fp16 out) ============
__global__ void agg_kernel(const __half* __restrict__ h,
                           const int* __restrict__ rowptr,
                           const int* __restrict__ col,
                           const float* __restrict__ dinv,
                           const float* __restrict__ bias,
                           __half* __restrict__ out, int n) {
    int warp = (blockIdx.x * blockDim.x + threadIdx.x) >> 5;
    int lane = threadIdx.x & 31;
    if (warp >= n) return;
    int beg = rowptr[warp], end = rowptr[warp + 1];
    float dv = dinv[warp];

    const uint2 sv = *(const uint2*)(h + (long)warp * 128 + lane * 4);
    float2 s0f = __half22float2(*(const __half2*)&sv.x);
    float2 s1f = __half22float2(*(const __half2*)&sv.y);
    float4 acc = make_float4(dv * s0f.x, dv * s0f.y, dv * s1f.x, dv * s1f.y);

    int e = beg;
    for (; e + 8 <= end; e += 8) {
        int c[8];
#pragma unroll
        for (int j = 0; j < 8; j++) c[j] = col[e + j];
        float w[8];
#pragma unroll
        for (int j = 0; j < 8; j++) w[j] = dinv[c[j]];
        uint2 rv[8];
#pragma unroll
        for (int j = 0; j < 8; j++)
            rv[j] = *(const uint2*)(h + (long)c[j] * 128 + lane * 4);
#pragma unroll
        for (int j = 0; j < 8; j++) {
            float2 a = __half22float2(*(const __half2*)&rv[j].x);
            float2 b = __half22float2(*(const __half2*)&rv[j].y);
            acc.x = fmaf(w[j], a.x, acc.x);
            acc.y = fmaf(w[j], a.y, acc.y);
            acc.z = fmaf(w[j], b.x, acc.z);
            acc.w = fmaf(w[j], b.y, acc.w);
        }
    }
    for (; e < end; e++) {
        int s = col[e];
        float w = dinv[s];
        uint2 rv = *(const uint2*)(h + (long)s * 128 + lane * 4);
        float2 a = __half22float2(*(const __half2*)&rv.x);
        float2 b = __half22float2(*(const __half2*)&rv.y);
        acc.x = fmaf(w, a.x, acc.x);
        acc.y = fmaf(w, a.y, acc.y);
        acc.z = fmaf(w, b.x, acc.z);
        acc.w = fmaf(w, b.y, acc.w);
    }
    float4 bb = *(const float4*)&bias[lane * 4];
    __half2 p0 = __floats2half2_rn(acc.x * dv + bb.x, acc.y * dv + bb.y);
    __half2 p1 = __floats2half2_rn(acc.z * dv + bb.z, acc.w * dv + bb.w);
    uint32_t* o = (uint32_t*)(out + (long)warp * 128 + lane * 4);
    o[0] = *(uint32_t*)&p0;
    o[1] = *(uint32_t*)&p1;
}

// ==================== batch aggregation in x1-space =========================
__global__ void agg_batch_h_kernel(const __half* __restrict__ x1,
                                   const int* __restrict__ rowptr,
                                   const int* __restrict__ col,
                                   const float* __restrict__ dinv,
                                   const int* __restrict__ head,
                                   const int* __restrict__ tail,
                                   float* __restrict__ Z) {
    int gw = (blockIdx.x * blockDim.x + threadIdx.x) >> 5;
    int lane = threadIdx.x & 31;
    if (gw >= 2 * NBATCH) return;
    int node = (gw < NBATCH) ? head[gw] : tail[gw - NBATCH];

    int beg = rowptr[node], end = rowptr[node + 1];
    float dv = dinv[node];

    const uint2 sv = *(const uint2*)(x1 + (long)node * 128 + lane * 4);
    float2 s0f = __half22float2(*(const __half2*)&sv.x);
    float2 s1f = __half22float2(*(const __half2*)&sv.y);
    float4 acc = make_float4(dv * s0f.x, dv * s0f.y, dv * s1f.x, dv * s1f.y);

    int e = beg;
    for (; e + 8 <= end; e += 8) {
        int c[8];
#pragma unroll
        for (int j = 0; j < 8; j++) c[j] = col[e + j];
        float w[8];
#pragma unroll
        for (int j = 0; j < 8; j++) w[j] = dinv[c[j]];
        uint2 rv[8];
#pragma unroll
        for (int j = 0; j < 8; j++)
            rv[j] = *(const uint2*)(x1 + (long)c[j] * 128 + lane * 4);
#pragma unroll
        for (int j = 0; j < 8; j++) {
            float2 a = __half22float2(*(const __half2*)&rv[j].x);
            float2 b = __half22float2(*(const __half2*)&rv[j].y);
            acc.x = fmaf(w[j], a.x, acc.x);
            acc.y = fmaf(w[j], a.y, acc.y);
            acc.z = fmaf(w[j], b.x, acc.z);
            acc.w = fmaf(w[j], b.y, acc.w);
        }
    }
    for (; e < end; e++) {
        int s = col[e];
        float w = dinv[s];
        uint2 rv = *(const uint2*)(x1 + (long)s * 128 + lane * 4);
        float2 a = __half22float2(*(const __half2*)&rv.x);
        float2 b = __half22float2(*(const __half2*)&rv.y);
        acc.x = fmaf(w, a.x, acc.x);
        acc.y = fmaf(w, a.y, acc.y);
        acc.z = fmaf(w, b.x, acc.z);
        acc.w = fmaf(w, b.y, acc.w);
    }
    *(float4*)&Z[(long)gw * 128 + lane * 4] =
        make_float4(acc.x * dv, acc.y * dv, acc.z * dv, acc.w * dv);
}

// ==================== scorer (cp.async double-buffered S) ===================
__global__ void __launch_bounds__(256)
score_mma(const __half* __restrict__ Thi,
          const __half* __restrict__ Sh,
          const float* __restrict__ Hg, float* __restrict__ out) {
    extern __shared__ char smem[];
    __half* sAh = (__half*)smem;
    __half* sB0 = sAh + 128 * LDT;
    __half* sB1 = sB0 + 128 * LDT;
    float* Hs = (float*)(sB1 + 128 * LDT);       // [128][LDH]
    float* out_s = Hs + 128 * LDH;               // [RGROUP][128]

    int t = threadIdx.x, wid = t >> 5, l = t & 31;
    int tile = blockIdx.x, rg = blockIdx.y;
    int rr = t >> 1, hc = (t & 1) * 64;

    uint32_t sB_u[2] = { smem_u32(sB0), smem_u32(sB1) };
    uint32_t stage_dst_base = (uint32_t)((rr * LDT + hc) * 2);

    // prefetch S for first relation of this group
    {
        const __half* src = Sh + (long)(rg * RGROUP) * 16384 + rr * 128 + hc;
        uint32_t dst = sB_u[0] + stage_dst_base;
#pragma unroll
        for (int g = 0; g < 8; g++)
            CP_ASYNC16(dst + g * 16, src + g * 8);
        CP_COMMIT();
    }

    // stage tail tile + head tile; zero out_s
    {
        long base = (long)(tile * 128 + rr) * 128 + hc;
#pragma unroll
        for (int g = 0; g < 8; g++) {
            int so = rr * LDT + hc + g * 8;
            *(uint4*)&sAh[so] = *(const uint4*)&Thi[base + g * 8];
        }
        const float* hr = Hg + (long)(tile * 128 + rr) * 128 + hc;
#pragma unroll
        for (int g = 0; g < 8; g++) {
            float4 v0 = *(const float4*)&hr[g * 8];
            float4 v1 = *(const float4*)&hr[g * 8 + 4];
            int so = rr * LDH + hc + g * 8;
            *(float4*)&Hs[so] = v0;
            *(float4*)&Hs[so + 4] = v1;
        }
        if (t < 128)
#pragma unroll
            for (int i = 0; i < RGROUP; i++) out_s[i * 128 + t] = 0.f;
    }

    uint32_t sAh_u = smem_u32(sAh);

    int wm = wid >> 2, wn = wid & 3;
    int m0 = wm * 64, n0 = wn * 32;
    int arow = l & 15, acol8 = (l >> 4) * 8;
    int brow = (l & 7) + (l >> 4) * 8, bcol = ((l >> 3) & 1) * 8;
    int r01 = l >> 2, cql = (l & 3) * 2;

    int rmax = NREL - rg * RGROUP;
    if (rmax > RGROUP) rmax = RGROUP;

    __syncthreads();

    for (int i = 0; i < rmax; i++) {
        bool pf = (i + 1 < rmax);
        if (pf) {
            const __half* src = Sh + (long)(rg * RGROUP + i + 1) * 16384 + rr * 128 + hc;
            uint32_t dst = sB_u[(i + 1) & 1] + stage_dst_base;
#pragma unroll
            for (int g = 0; g < 8; g++)
                CP_ASYNC16(dst + g * 16, src + g * 8);
            CP_COMMIT();
            CP_WAIT(1);
        } else {
            CP_WAIT(0);
        }
        __syncthreads();

        uint32_t sBc = sB_u[i & 1];
        float acc[4][4][4];
#pragma unroll
        for (int mf = 0; mf < 4; mf++)
#pragma unroll
            for (int nf = 0; nf < 4; nf++)
#pragma unroll
                for (int c = 0; c < 4; c++) acc[mf][nf][c] = 0.f;

#pragma unroll
        for (int ks = 0; ks < 8; ks++) {
            int k0 = ks * 16;
            uint32_t ah[4][4], bf[2][4];
#pragma unroll
            for (int mf = 0; mf < 4; mf++) {
                uint32_t off = (uint32_t)(((m0 + mf * 16 + arow) * LDT + k0 + acol8) * 2);
                ldm_x4(ah[mf], sAh_u + off);
            }
#pragma unroll
            for (int nh = 0; nh < 2; nh++) {
                uint32_t off = (uint32_t)(((n0 + nh * 16 + brow) * LDT + k0 + bcol) * 2);
                ldm_x4(bf[nh], sBc + off);
            }
#pragma unroll
            for (int mf = 0; mf < 4; mf++)
#pragma unroll
                for (int nf = 0; nf < 4; nf++) {
                    const uint32_t* bp = &bf[nf >> 1][(nf & 1) * 2];
                    mma16816(acc[mf][nf], ah[mf], bp);
                }
        }

        float part[4][2];
#pragma unroll
        for (int mf = 0; mf < 4; mf++) { part[mf][0] = 0.f; part[mf][1] = 0.f; }
#pragma unroll
        for (int mf = 0; mf < 4; mf++) {
            int ra = m0 + mf * 16 + r01;
#pragma unroll
            for (int nf = 0; nf < 4; nf++) {
                int col = n0 + nf * 8 + cql;
                float2 h0 = *(float2*)&Hs[ra * LDH + col];
                float2 h1 = *(float2*)&Hs[(ra + 8) * LDH + col];
                part[mf][0] += acc[mf][nf][0] * h0.x + acc[mf][nf][1] * h0.y;
                part[mf][1] += acc[mf][nf][2] * h1.x + acc[mf][nf][3] * h1.y;
            }
        }
#pragma unroll
        for (int mf = 0; mf < 4; mf++) {
#pragma unroll
            for (int hh = 0; hh < 2; hh++) {
                part[mf][hh] += __shfl_xor_sync(0xffffffffu, part[mf][hh], 1);
                part[mf][hh] += __shfl_xor_sync(0xffffffffu, part[mf][hh], 2);
            }
        }
        float* os = out_s + i * 128;
        if ((l & 3) == 0) {
#pragma unroll
            for (int mf = 0; mf < 4; mf++) {
                atomicAdd(&os[m0 + mf * 16 + r01], part[mf][0]);
                atomicAdd(&os[m0 + mf * 16 + r01 + 8], part[mf][1]);
            }
        }
        __syncthreads();
    }

    if (t < 128) {
        long orow = (long)(tile * 128 + t) * NREL + rg * RGROUP;
        for (int i = 0; i < rmax; i++)
            out[orow + i] = out_s[i * 128 + t];
    }
}

// ==================== launch ================================================
extern "C" void kernel_launch(void* const* d_in, const int* in_sizes, int n_in,
                              void* d_out, int out_size) {
    const float* init_emb = (const float*)d_in[0];
    const float* W1       = (const float*)d_in[1];
    const float* b1       = (const float*)d_in[2];
    const float* W2       = (const float*)d_in[3];
    const float* b2       = (const float*)d_in[4];
    const float* Rp       = (const float*)d_in[5];
    const float* Mp       = (const float*)d_in[6];
    const int*   head     = (const int*)d_in[7];
    const int*   tail     = (const int*)d_in[8];
    const int*   ei       = (const int*)d_in[9];
    float* out = (float*)d_out;

    const int* src = ei;
    const int* dst = ei + NEDGES;

    float *p_Z, *p_dinv, *p_T, *p_head;
    __half *p_hh, *p_x1h, *p_WTh, *p_WTl, *p_Rh, *p_Rl, *p_Sh, *p_thi;
    int *p_cnt, *p_bsum, *p_rowptr, *p_cur, *p_col;
    cudaGetSymbolAddress((void**)&p_hh, g_hh);
    cudaGetSymbolAddress((void**)&p_x1h, g_x1h);
    cudaGetSymbolAddress((void**)&p_Z, g_Z);
    cudaGetSymbolAddress((void**)&p_dinv, g_dinv);
    cudaGetSymbolAddress((void**)&p_cnt, g_cnt);
    cudaGetSymbolAddress((void**)&p_bsum, g_bsum);
    cudaGetSymbolAddress((void**)&p_rowptr, g_rowptr);
    cudaGetSymbolAddress((void**)&p_cur, g_cur);
    cudaGetSymbolAddress((void**)&p_col, g_col);
    cudaGetSymbolAddress((void**)&p_T, g_T);
    cudaGetSymbolAddress((void**)&p_WTh, g_WTh);
    cudaGetSymbolAddress((void**)&p_WTl, g_WTl);
    cudaGetSymbolAddress((void**)&p_Rh, g_Rh);
    cudaGetSymbolAddress((void**)&p_Rl, g_Rl);
    cudaGetSymbolAddress((void**)&p_Sh, g_Sh);
    cudaGetSymbolAddress((void**)&p_head, g_head);
    cudaGetSymbolAddress((void**)&p_thi, g_thi);

    const int GEMM_SMEM3 = 3 * 128 * LDT * 2;                       // 104448
    const int GEMM_SMEM4 = 4 * 128 * LDT * 2;                       // 139264
    const int SCORE_SMEM = 3 * 128 * LDT * 2 + 128 * LDH * 4 + RGROUP * 128 * 4;
    cudaFuncSetAttribute(gemm_mma,       cudaFuncAttributeMaxDynamicSharedMemorySize, GEMM_SMEM4);
    cudaFuncSetAttribute(gemm_batch_mma, cudaFuncAttributeMaxDynamicSharedMemorySize, GEMM_SMEM3);
    cudaFuncSetAttribute(score_mma,      cudaFuncAttributeMaxDynamicSharedMemorySize, SCORE_SMEM);

    // ---- fork/join streams for capture-parallel branches ----
    cudaStream_t sB, sC;
    cudaStreamCreateWithFlags(&sB, cudaStreamNonBlocking);
    cudaStreamCreateWithFlags(&sC, cudaStreamNonBlocking);
    cudaEvent_t evRoot, evW, evCSR, evS;
    cudaEventCreateWithFlags(&evRoot, cudaEventDisableTiming);
    cudaEventCreateWithFlags(&evW,    cudaEventDisableTiming);
    cudaEventCreateWithFlags(&evCSR,  cudaEventDisableTiming);
    cudaEventCreateWithFlags(&evS,    cudaEventDisableTiming);

    cudaEventRecord(evRoot, 0);

    // --- branch B: CSR build (multi-block scan; memset for zero) ---
    cudaStreamWaitEvent(sB, evRoot, 0);
    cudaMemsetAsync(p_cnt, 0, NNODES * sizeof(int), sB);
    count_kernel<<<(NEDGES / 4 + 255) / 256, 256, 0, sB>>>(
        (const int4*)dst, p_cnt, NEDGES / 4);
    scanA_kernel<<<NSCANB, 256, 0, sB>>>(p_cnt, p_bsum, NNODES);
    scanB_kernel<<<1, 256, 0, sB>>>(p_bsum, NSCANB);
    scanC_kernel<<<NSCANB, 256, 0, sB>>>(p_cnt, p_bsum, p_rowptr, p_cur,
                                         p_dinv, NNODES);
    fill_kernel<<<(NEDGES / 4 + 255) / 256, 256, 0, sB>>>(
        (const int4*)src, (const int4*)dst, p_cur, p_col, NEDGES / 4);
    cudaEventRecord(evCSR, sB);

    // --- main: weight prep ---
    prepW_kernel<<<3, 128>>>(W1, W2, Mp, p_WTh, p_WTl);
    cudaEventRecord(evW, 0);

    // --- branch C: relation prep + S precompute (3-pass, hidden) ---
    cudaStreamWaitEvent(sC, evRoot, 0);
    prepR_kernel<<<(NREL * 16384 / 8 + 255) / 256, 256, 0, sC>>>(Rp, p_Rh, p_Rl);
    cudaStreamWaitEvent(sC, evW, 0);
    gemm_mma<<<dim3(1, NREL), 256, GEMM_SMEM4, sC>>>(
        Rp, 16384, p_WTh + 2 * 16384, p_WTl + 2 * 16384, 0,
        p_T, 16384, nullptr, 0, 128);
    gemm_mma<<<dim3(1, NREL), 256, GEMM_SMEM4, sC>>>(
        p_T, 16384, p_Rh, p_Rl, 16384,
        nullptr, 0, p_Sh, 16384, 128);
    cudaEventRecord(evS, sC);

    int ntiles = (NNODES + 127) / 128;  // 391
    int agg_blocks = (NNODES * 32 + 255) / 256;

    // --- main chain ---
    gemm_mma<<<dim3(ntiles, 1), 256, GEMM_SMEM3>>>(
        init_emb, 0, p_WTh, nullptr, 0, nullptr, 0,
        p_hh, 0, NNODES);
    cudaStreamWaitEvent(0, evCSR, 0);
    agg_kernel<<<agg_blocks, 256>>>(p_hh, p_rowptr, p_col, p_dinv, b1, p_x1h, NNODES);
    agg_batch_h_kernel<<<(2 * NBATCH * 32 + 255) / 256, 256>>>(
        p_x1h, p_rowptr, p_col, p_dinv, head, tail, p_Z);
    gemm_batch_mma<<<2 * NBATCH / 128, 256, GEMM_SMEM3>>>(
        p_Z, p_WTh + 16384, b2, p_head, p_thi);

    cudaStreamWaitEvent(0, evS, 0);
    score_mma<<<dim3(NBATCH / 128, (NREL + RGROUP - 1) / RGROUP), 256, SCORE_SMEM>>>(
        p_thi, p_Sh, p_head, out);

    cudaStreamDestroy(sB);
    cudaStreamDestroy(sC);
    cudaEventDestroy(evRoot);
    cudaEventDestroy(evW);
    cudaEventDestroy(evCSR);
    cudaEventDestroy(evS);
}